// round 10
// baseline (speedup 1.0000x reference)
#include <cuda_runtime.h>
#include <cuda_fp16.h>
#include <cstdint>

// ============ sm_103-safe primitives ============
__device__ __forceinline__ uint32_t smem_u32(const void* p) {
    uint32_t a;
    asm("{ .reg .u64 t; cvta.to.shared.u64 t, %1; cvt.u32.u64 %0, t; }" : "=r"(a) : "l"(p));
    return a;
}
__device__ __forceinline__ void ldsm4(uint32_t r[4], uint32_t addr) {
    asm volatile("ldmatrix.sync.aligned.m8n8.x4.shared.b16 {%0,%1,%2,%3}, [%4];"
                 : "=r"(r[0]), "=r"(r[1]), "=r"(r[2]), "=r"(r[3]) : "r"(addr));
}
__device__ __forceinline__ void ldsm4t(uint32_t r[4], uint32_t addr) {
    asm volatile("ldmatrix.sync.aligned.m8n8.x4.trans.shared.b16 {%0,%1,%2,%3}, [%4];"
                 : "=r"(r[0]), "=r"(r[1]), "=r"(r[2]), "=r"(r[3]) : "r"(addr));
}
__device__ __forceinline__ void mma16816(float c[4], const uint32_t a[4],
                                         uint32_t b0, uint32_t b1) {
    asm volatile(
        "mma.sync.aligned.m16n8k16.row.col.f32.f16.f16.f32 "
        "{%0,%1,%2,%3},{%4,%5,%6,%7},{%8,%9},{%0,%1,%2,%3};"
        : "+f"(c[0]), "+f"(c[1]), "+f"(c[2]), "+f"(c[3])
        : "r"(a[0]), "r"(a[1]), "r"(a[2]), "r"(a[3]), "r"(b0), "r"(b1));
}
__device__ __forceinline__ uint32_t pack2h(__half lo, __half hi) {
    return ((uint32_t)__half_as_ushort(hi) << 16) | (uint32_t)__half_as_ushort(lo);
}
__device__ __forceinline__ void split4h(float4 v, uint2& h, uint2& l) {
    __half h0 = __float2half_rn(v.x), h1 = __float2half_rn(v.y);
    __half h2 = __float2half_rn(v.z), h3 = __float2half_rn(v.w);
    __half l0 = __float2half_rn(v.x - __half2float(h0));
    __half l1 = __float2half_rn(v.y - __half2float(h1));
    __half l2 = __float2half_rn(v.z - __half2float(h2));
    __half l3 = __float2half_rn(v.w - __half2float(h3));
    h = make_uint2(pack2h(h0, h1), pack2h(h2, h3));
    l = make_uint2(pack2h(l0, l1), pack2h(l2, l3));
}
__device__ __forceinline__ uint2 cvt4h(float4 v) {
    return make_uint2(pack2h(__float2half_rn(v.x), __float2half_rn(v.y)),
                      pack2h(__float2half_rn(v.z), __float2half_rn(v.w)));
}
__device__ __forceinline__ void cpa16(uint32_t dst, const void* src) {
    asm volatile("cp.async.cg.shared.global [%0], [%1], 16;" :: "r"(dst), "l"(src) : "memory");
}
#define CP_COMMIT() asm volatile("cp.async.commit_group;" ::: "memory")
#define CP_WAIT1()  asm volatile("cp.async.wait_group 1;" ::: "memory")
#define CP_WAIT0()  asm volatile("cp.async.wait_group 0;" ::: "memory")
#define SWZ64A(o) ((o) ^ (((o) >> 2) & 0x70))
#define SWZ128(o) ((o) ^ (((o) >> 3) & 0x70))
#define SWZ256(o) ((o) ^ (((o) >> 4) & 0x70))

// ============ problem constants ============
#define FIN  1024
#define SEQ  128
#define CH   32
#define NC   32

// ============ pre-split global staging (fp16) ============
__device__ __align__(16) __half g_WqH[1024 * 1024];
__device__ __align__(16) __half g_WqL[1024 * 1024];
__device__ __align__(16) __half g_WkH[1024 * 1024];
__device__ __align__(16) __half g_WkL[1024 * 1024];
__device__ __align__(16) __half g_x[256 * 1024 * 128];

__global__ void __launch_bounds__(256) prep_w_kernel(const float* __restrict__ Wq,
                                                     const float* __restrict__ Wk) {
    int i = blockIdx.x * 256 + threadIdx.x;
    float4 v = ((const float4*)Wq)[i];
    uint2 h, l;
    split4h(v, h, l);
    ((uint2*)g_WqH)[i] = h; ((uint2*)g_WqL)[i] = l;
    v = ((const float4*)Wk)[i];
    split4h(v, h, l);
    ((uint2*)g_WkH)[i] = h; ((uint2*)g_WkL)[i] = l;
}
__global__ void __launch_bounds__(256) prep_x_kernel(const float* __restrict__ x) {
    size_t i = (size_t)blockIdx.x * 256 + threadIdx.x;
    ((uint2*)g_x)[i] = cvt4h(((const float4*)x)[i]);
}

// ============ SMEM layout (bytes) ============
// 3-stage chunk buffers: [Wh 16K | Wl 16K | x 8K] x 3 = 120K
#define BUF_SZ  40960
#define BW_H    0
#define BW_L    16384
#define BX_S    32768
#define KT_L    0              // overlays dead buffer region after mainloop
#define QT_H    122880
#define QT_L    155648
#define KT_H    188416
#define W_SM    221184
#define BQ_SM   222208
#define BK_SM   222720
#define WO_SM   223232
#define SMEM_TOTAL 223744

__global__ void __launch_bounds__(256, 1)
Attention_75402445849133_kernel(const float* __restrict__ x,
                                const float* __restrict__ bq, const float* __restrict__ bk,
                                const float* __restrict__ Wo, const float* __restrict__ bo,
                                float* __restrict__ out)
{
    extern __shared__ char smem[];
    const uint32_t sbase = smem_u32(smem);
    const int tid = threadIdx.x;
    const int w   = tid >> 5;
    const int lid = tid & 31;
    const int gq  = lid >> 2;
    const int tq  = lid & 3;
    const int g   = blockIdx.x;
    const int b   = blockIdx.y;

    float* wsm = (float*)(smem + W_SM);
    float* bqs = (float*)(smem + BQ_SM);
    float* bks = (float*)(smem + BK_SM);
    float* wos = (float*)(smem + WO_SM);
    if (tid < 128) {
        bqs[tid] = bq[g * 128 + tid];
        bks[tid] = bk[g * 128 + tid];
        wos[tid] = Wo[tid];
    }
    wsm[tid] = 0.0f;

    const float* xb = x + (size_t)b * FIN * SEQ;
    const __half* xbh = g_x + (size_t)b * FIN * SEQ;

    const int m0 = (w & 3) * 64;
    const int n0 = (w >> 2) * 64;

    // ---- cp.async coordinates ----
    const __half* wbH[4];
    const __half* wbL[4];
    uint32_t wsoff[4];
    #pragma unroll
    for (int j = 0; j < 4; j++) {
        int wi = j * 256 + tid;
        int row = wi >> 2, cg = wi & 3;
        wsoff[j] = SWZ64A((uint32_t)(row * 64 + cg * 16));
        int isq = (row < 128);
        int rl  = row & 127;
        wbH[j] = (isq ? g_WqH : g_WkH) + (size_t)(g * 128 + rl) * FIN + cg * 8;
        wbL[j] = (isq ? g_WqL : g_WkL) + (size_t)(g * 128 + rl) * FIN + cg * 8;
    }
    uint32_t xsoff[2];
    int xrr[2], xsg[2];
    #pragma unroll
    for (int j = 0; j < 2; j++) {
        int xi = j * 256 + tid;
        xrr[j] = xi >> 4; xsg[j] = xi & 15;
        xsoff[j] = SWZ256((uint32_t)(xrr[j] * 256 + xsg[j] * 16));
    }

    float creg[4][8][4];
    #pragma unroll
    for (int a = 0; a < 4; a++)
        #pragma unroll
        for (int n = 0; n < 8; n++)
            #pragma unroll
            for (int j = 0; j < 4; j++) creg[a][n][j] = 0.f;

    // prologue: issue chunks 0 and 1 into buffers 0,1
    #pragma unroll
    for (int j = 0; j < 4; j++) {
        cpa16(sbase + BW_H + wsoff[j], wbH[j]);
        cpa16(sbase + BW_L + wsoff[j], wbL[j]);
    }
    #pragma unroll
    for (int j = 0; j < 2; j++)
        cpa16(sbase + BX_S + xsoff[j], xbh + xrr[j] * SEQ + xsg[j] * 8);
    CP_COMMIT();
    {
        const uint32_t nb = sbase + BUF_SZ;
        #pragma unroll
        for (int j = 0; j < 4; j++) {
            cpa16(nb + BW_H + wsoff[j], wbH[j] + CH);
            cpa16(nb + BW_L + wsoff[j], wbL[j] + CH);
        }
        #pragma unroll
        for (int j = 0; j < 2; j++)
            cpa16(nb + BX_S + xsoff[j], xbh + (size_t)(CH + xrr[j]) * SEQ + xsg[j] * 8);
        CP_COMMIT();
    }

    // ================= fused Q+K projection mainloop, 1 barrier/chunk ==========
    int bufIdx = 0;
    #pragma unroll 1
    for (int kc = 0; kc < NC; kc++) {
        if (kc < NC - 1) { CP_WAIT1(); } else { CP_WAIT0(); }
        __syncthreads();   // chunk kc visible to all; all reads of buf (kc-1)%3 done

        if (kc + 2 < NC) {
            int nIdx = bufIdx + 2; if (nIdx >= 3) nIdx -= 3;
            const uint32_t nb = sbase + nIdx * BUF_SZ;
            const int kn = (kc + 2) * CH;
            #pragma unroll
            for (int j = 0; j < 4; j++) {
                cpa16(nb + BW_H + wsoff[j], wbH[j] + kn);
                cpa16(nb + BW_L + wsoff[j], wbL[j] + kn);
            }
            #pragma unroll
            for (int j = 0; j < 2; j++)
                cpa16(nb + BX_S + xsoff[j], xbh + (size_t)(kn + xrr[j]) * SEQ + xsg[j] * 8);
            CP_COMMIT();
        }

        const uint32_t bufb = sbase + bufIdx * BUF_SZ;
        #pragma unroll
        for (int ks = 0; ks < 2; ks++) {
            const int k0 = ks * 16;
            uint32_t aH[4][4], aL[4][4];
            #pragma unroll
            for (int mt = 0; mt < 4; mt++) {
                int row = m0 + mt * 16 + (lid & 15);
                int col = k0 + ((lid >> 4) << 3);
                uint32_t off = SWZ64A((uint32_t)(row * 64 + col * 2));
                ldsm4(aH[mt], bufb + BW_H + off);
                ldsm4(aL[mt], bufb + BW_L + off);
            }
            const int tL  = lid >> 3;
            const int krw = k0 + ((tL & 1) << 3) + (lid & 7);
            uint32_t bCur[4], bNxt[4];
            {
                int nc = n0 + ((tL >> 1) << 3);
                ldsm4t(bCur, bufb + BX_S + SWZ256((uint32_t)(krw * 256 + nc * 2)));
            }
            #pragma unroll
            for (int np = 0; np < 4; np++) {
                if (np < 3) {
                    int nc = n0 + (np + 1) * 16 + ((tL >> 1) << 3);
                    ldsm4t(bNxt, bufb + BX_S + SWZ256((uint32_t)(krw * 256 + nc * 2)));
                }
                #pragma unroll
                for (int mt = 0; mt < 4; mt++) mma16816(creg[mt][np * 2],     aH[mt], bCur[0], bCur[1]);
                #pragma unroll
                for (int mt = 0; mt < 4; mt++) mma16816(creg[mt][np * 2 + 1], aH[mt], bCur[2], bCur[3]);
                #pragma unroll
                for (int mt = 0; mt < 4; mt++) mma16816(creg[mt][np * 2],     aL[mt], bCur[0], bCur[1]);
                #pragma unroll
                for (int mt = 0; mt < 4; mt++) mma16816(creg[mt][np * 2 + 1], aL[mt], bCur[2], bCur[3]);
                #pragma unroll
                for (int j = 0; j < 4; j++) bCur[j] = bNxt[j];
            }
        }
        if (++bufIdx == 3) bufIdx = 0;
    }
    __syncthreads();   // all reads of final buffers done before KT_L overlay writes

    // ---- writeback: stacked C -> qT / kT split fp16 (+bias; q scaled 1/8) ----
    {
        #pragma unroll
        for (int mt = 0; mt < 4; mt++)
            #pragma unroll
            for (int rj = 0; rj < 2; rj++) {
                int m = m0 + mt * 16 + rj * 8 + gq;
                int isq = (m < 128);
                int mloc = m & 127;
                float bias = isq ? bqs[mloc] : bks[mloc];
                int head = mloc >> 6, d = mloc & 63;
                char* dh = smem + (isq ? QT_H : KT_H) + head * 16384;
                char* dl = smem + (isq ? QT_L : KT_L) + head * 16384;
                #pragma unroll
                for (int nt = 0; nt < 8; nt++)
                    #pragma unroll
                    for (int jj = 0; jj < 2; jj++) {
                        int n = n0 + nt * 8 + tq * 2 + jj;
                        float v = creg[mt][nt][rj * 2 + jj] + bias;
                        if (isq) v *= 0.125f;
                        __half h = __float2half_rn(v);
                        __half l = __float2half_rn(v - __half2float(h));
                        uint32_t off = SWZ128((uint32_t)(n * 128 + d * 2));
                        *(__half*)(dh + off) = h;
                        *(__half*)(dl + off) = l;
                    }
            }
    }
    __syncthreads();

    // ================= Phase 2: scores (3-term fp16) + softmax + w reduction ====
    {
        const int head = w >> 2;
        const int sb0  = (w & 3) * 32;
        const uint32_t qh = sbase + QT_H + head * 16384;
        const uint32_t ql = sbase + QT_L + head * 16384;
        const uint32_t kh = sbase + KT_H + head * 16384;
        const uint32_t kl = sbase + KT_L + head * 16384;

        float wacc[16][2];
        #pragma unroll
        for (int nt = 0; nt < 16; nt++) { wacc[nt][0] = 0.f; wacc[nt][1] = 0.f; }

        #pragma unroll 1
        for (int chunk = 0; chunk < 2; chunk++) {
            const int s0 = sb0 + chunk * 16;
            float sc[16][4];
            #pragma unroll
            for (int nt = 0; nt < 16; nt++)
                #pragma unroll
                for (int j = 0; j < 4; j++) sc[nt][j] = 0.f;

            #pragma unroll
            for (int ks = 0; ks < 4; ks++) {
                const int k0 = ks * 16;
                uint32_t aH[4], aL[4];
                {
                    int row = s0 + (lid & 15);
                    int col = k0 + ((lid >> 4) << 3);
                    uint32_t off = SWZ128((uint32_t)(row * 128 + col * 2));
                    ldsm4(aH, qh + off);
                    ldsm4(aL, ql + off);
                }
                #pragma unroll
                for (int npp = 0; npp < 4; npp++) {
                    int tL = lid >> 3;
                    int ccol = k0 + ((tL & 1) << 3);
                    int r0 = (npp * 2) * 16 + ((tL >> 1) << 3) + (lid & 7);
                    int r1 = (npp * 2 + 1) * 16 + ((tL >> 1) << 3) + (lid & 7);
                    uint32_t bH0[4], bL0[4], bH1[4], bL1[4];
                    ldsm4(bH0, kh + SWZ128((uint32_t)(r0 * 128 + ccol * 2)));
                    ldsm4(bL0, kl + SWZ128((uint32_t)(r0 * 128 + ccol * 2)));
                    ldsm4(bH1, kh + SWZ128((uint32_t)(r1 * 128 + ccol * 2)));
                    ldsm4(bL1, kl + SWZ128((uint32_t)(r1 * 128 + ccol * 2)));
                    float* s00 = sc[npp * 4 + 0];
                    float* s01 = sc[npp * 4 + 1];
                    float* s10 = sc[npp * 4 + 2];
                    float* s11 = sc[npp * 4 + 3];
                    mma16816(s00, aH, bH0[0], bH0[1]);
                    mma16816(s01, aH, bH0[2], bH0[3]);
                    mma16816(s10, aH, bH1[0], bH1[1]);
                    mma16816(s11, aH, bH1[2], bH1[3]);
                    mma16816(s00, aH, bL0[0], bL0[1]);
                    mma16816(s01, aH, bL0[2], bL0[3]);
                    mma16816(s10, aH, bL1[0], bL1[1]);
                    mma16816(s11, aH, bL1[2], bL1[3]);
                    mma16816(s00, aL, bH0[0], bH0[1]);
                    mma16816(s01, aL, bH0[2], bH0[3]);
                    mma16816(s10, aL, bH1[0], bH1[1]);
                    mma16816(s11, aL, bH1[2], bH1[3]);
                }
            }
            float mx0 = -1e30f, mx1 = -1e30f;
            #pragma unroll
            for (int nt = 0; nt < 16; nt++) {
                mx0 = fmaxf(mx0, fmaxf(sc[nt][0], sc[nt][1]));
                mx1 = fmaxf(mx1, fmaxf(sc[nt][2], sc[nt][3]));
            }
            mx0 = fmaxf(mx0, __shfl_xor_sync(0xffffffffu, mx0, 1));
            mx0 = fmaxf(mx0, __shfl_xor_sync(0xffffffffu, mx0, 2));
            mx1 = fmaxf(mx1, __shfl_xor_sync(0xffffffffu, mx1, 1));
            mx1 = fmaxf(mx1, __shfl_xor_sync(0xffffffffu, mx1, 2));
            float Z0 = 0.f, Z1 = 0.f;
            #pragma unroll
            for (int nt = 0; nt < 16; nt++) {
                sc[nt][0] = __expf(sc[nt][0] - mx0); Z0 += sc[nt][0];
                sc[nt][1] = __expf(sc[nt][1] - mx0); Z0 += sc[nt][1];
                sc[nt][2] = __expf(sc[nt][2] - mx1); Z1 += sc[nt][2];
                sc[nt][3] = __expf(sc[nt][3] - mx1); Z1 += sc[nt][3];
            }
            Z0 += __shfl_xor_sync(0xffffffffu, Z0, 1);
            Z0 += __shfl_xor_sync(0xffffffffu, Z0, 2);
            Z1 += __shfl_xor_sync(0xffffffffu, Z1, 1);
            Z1 += __shfl_xor_sync(0xffffffffu, Z1, 2);
            const float c0 = wos[s0 + gq]     / Z0;
            const float c1 = wos[s0 + 8 + gq] / Z1;
            #pragma unroll
            for (int nt = 0; nt < 16; nt++) {
                wacc[nt][0] += sc[nt][0] * c0 + sc[nt][2] * c1;
                wacc[nt][1] += sc[nt][1] * c0 + sc[nt][3] * c1;
            }
        }
        #pragma unroll
        for (int d = 4; d < 32; d <<= 1)
            #pragma unroll
            for (int nt = 0; nt < 16; nt++) {
                wacc[nt][0] += __shfl_xor_sync(0xffffffffu, wacc[nt][0], d);
                wacc[nt][1] += __shfl_xor_sync(0xffffffffu, wacc[nt][1], d);
            }
        if (lid < 4) {
            #pragma unroll
            for (int nt = 0; nt < 16; nt++) {
                atomicAdd(&wsm[head * 128 + nt * 8 + 2 * lid],     wacc[nt][0]);
                atomicAdd(&wsm[head * 128 + nt * 8 + 2 * lid + 1], wacc[nt][1]);
            }
        }
    }
    __syncthreads();

    // ================= Phase 3: out[b, g*128+f] = sum_t w[head][t]*x[b,f,t] + bo
    if (tid < 128) {
        const float* wv2 = wsm + (tid >> 6) * 128;
        const float4* x4 = (const float4*)(xb + (size_t)(g * 128 + tid) * SEQ);
        float acc = 0.f;
        #pragma unroll 8
        for (int t4 = 0; t4 < 32; t4++) {
            float4 xvv = x4[t4];
            acc += xvv.x * wv2[t4 * 4 + 0] + xvv.y * wv2[t4 * 4 + 1]
                 + xvv.z * wv2[t4 * 4 + 2] + xvv.w * wv2[t4 * 4 + 3];
        }
        out[(size_t)b * FIN + g * 128 + tid] = acc + bo[0];
    }
}

extern "C" void kernel_launch(void* const* d_in, const int* in_sizes, int n_in,
                              void* d_out, int out_size)
{
    (void)in_sizes; (void)n_in; (void)out_size;
    const float* x  = (const float*)d_in[0];
    const float* Wq = (const float*)d_in[1];
    const float* bq = (const float*)d_in[2];
    const float* Wk = (const float*)d_in[3];
    const float* bk = (const float*)d_in[4];
    const float* Wo = (const float*)d_in[5];
    const float* bo = (const float*)d_in[6];
    float* out = (float*)d_out;

    prep_w_kernel<<<1024, 256>>>(Wq, Wk);
    prep_x_kernel<<<32768, 256>>>(x);

    cudaFuncSetAttribute(Attention_75402445849133_kernel,
                         cudaFuncAttributeMaxDynamicSharedMemorySize, SMEM_TOTAL);
    dim3 grid(8, 256, 1);
    Attention_75402445849133_kernel<<<grid, 256, SMEM_TOTAL>>>(x, bq, bk, Wo, bo, out);
}

// round 11
// speedup vs baseline: 1.4723x; 1.4723x over previous
#include <cuda_runtime.h>
#include <cuda_fp16.h>
#include <cstdint>

// ============ sm_103-safe primitives ============
__device__ __forceinline__ uint32_t smem_u32(const void* p) {
    uint32_t a;
    asm("{ .reg .u64 t; cvta.to.shared.u64 t, %1; cvt.u32.u64 %0, t; }" : "=r"(a) : "l"(p));
    return a;
}
__device__ __forceinline__ void ldsm4(uint32_t r[4], uint32_t addr) {
    asm volatile("ldmatrix.sync.aligned.m8n8.x4.shared.b16 {%0,%1,%2,%3}, [%4];"
                 : "=r"(r[0]), "=r"(r[1]), "=r"(r[2]), "=r"(r[3]) : "r"(addr));
}
__device__ __forceinline__ void ldsm4t(uint32_t r[4], uint32_t addr) {
    asm volatile("ldmatrix.sync.aligned.m8n8.x4.trans.shared.b16 {%0,%1,%2,%3}, [%4];"
                 : "=r"(r[0]), "=r"(r[1]), "=r"(r[2]), "=r"(r[3]) : "r"(addr));
}
__device__ __forceinline__ void mma16816(float c[4], const uint32_t a[4],
                                         uint32_t b0, uint32_t b1) {
    asm volatile(
        "mma.sync.aligned.m16n8k16.row.col.f32.f16.f16.f32 "
        "{%0,%1,%2,%3},{%4,%5,%6,%7},{%8,%9},{%0,%1,%2,%3};"
        : "+f"(c[0]), "+f"(c[1]), "+f"(c[2]), "+f"(c[3])
        : "r"(a[0]), "r"(a[1]), "r"(a[2]), "r"(a[3]), "r"(b0), "r"(b1));
}
__device__ __forceinline__ uint32_t pack2h(__half lo, __half hi) {
    return ((uint32_t)__half_as_ushort(hi) << 16) | (uint32_t)__half_as_ushort(lo);
}
__device__ __forceinline__ uint2 cvt4h(float4 v) {
    return make_uint2(pack2h(__float2half_rn(v.x), __float2half_rn(v.y)),
                      pack2h(__float2half_rn(v.z), __float2half_rn(v.w)));
}
__device__ __forceinline__ void cpa16(uint32_t dst, const void* src) {
    asm volatile("cp.async.cg.shared.global [%0], [%1], 16;" :: "r"(dst), "l"(src) : "memory");
}
#define CP_COMMIT() asm volatile("cp.async.commit_group;" ::: "memory")
#define CP_WAIT1()  asm volatile("cp.async.wait_group 1;" ::: "memory")
#define CP_WAIT0()  asm volatile("cp.async.wait_group 0;" ::: "memory")
#define SWZ64A(o) ((o) ^ (((o) >> 2) & 0x70))
#define SWZ128(o) ((o) ^ (((o) >> 3) & 0x70))
#define SWZ256(o) ((o) ^ (((o) >> 4) & 0x70))

// ============ problem constants ============
#define FIN  1024
#define SEQ  128
#define CH   32
#define NC   32

// ============ pre-converted global staging (single fp16) ============
__device__ __align__(16) __half g_Wq[1024 * 1024];
__device__ __align__(16) __half g_Wk[1024 * 1024];
__device__ __align__(16) __half g_x[256 * 1024 * 128];

__global__ void __launch_bounds__(256) prep_w_kernel(const float* __restrict__ Wq,
                                                     const float* __restrict__ Wk) {
    int i = blockIdx.x * 256 + threadIdx.x;
    ((uint2*)g_Wq)[i] = cvt4h(((const float4*)Wq)[i]);
    ((uint2*)g_Wk)[i] = cvt4h(((const float4*)Wk)[i]);
}
__global__ void __launch_bounds__(256) prep_x_kernel(const float* __restrict__ x) {
    size_t i = (size_t)blockIdx.x * 256 + threadIdx.x;
    ((uint2*)g_x)[i] = cvt4h(((const float4*)x)[i]);
}

// ============ SMEM layout (bytes) ============
// 3-stage chunk buffers: [W 256x32 fp16 16K | x 32x128 fp16 8K] x 3 = 72K
#define BUF_SZ  24576
#define BW_S    0
#define BX_S    16384
#define KT_L    0              // overlays dead buffer region after mainloop
#define QT_H    73728
#define QT_L    106496
#define KT_H    139264
#define W_SM    172032
#define BQ_SM   173056
#define BK_SM   173568
#define WO_SM   174080
#define SMEM_TOTAL 174592

__global__ void __launch_bounds__(256, 1)
Attention_75402445849133_kernel(const float* __restrict__ x,
                                const float* __restrict__ bq, const float* __restrict__ bk,
                                const float* __restrict__ Wo, const float* __restrict__ bo,
                                float* __restrict__ out)
{
    extern __shared__ char smem[];
    const uint32_t sbase = smem_u32(smem);
    const int tid = threadIdx.x;
    const int w   = tid >> 5;
    const int lid = tid & 31;
    const int gq  = lid >> 2;
    const int tq  = lid & 3;
    const int g   = blockIdx.x;
    const int b   = blockIdx.y;

    float* wsm = (float*)(smem + W_SM);
    float* bqs = (float*)(smem + BQ_SM);
    float* bks = (float*)(smem + BK_SM);
    float* wos = (float*)(smem + WO_SM);
    if (tid < 128) {
        bqs[tid] = bq[g * 128 + tid];
        bks[tid] = bk[g * 128 + tid];
        wos[tid] = Wo[tid];
    }
    wsm[tid] = 0.0f;

    const float* xb = x + (size_t)b * FIN * SEQ;
    const __half* xbh = g_x + (size_t)b * FIN * SEQ;

    const int m0 = (w & 3) * 64;
    const int n0 = (w >> 2) * 64;

    // ---- cp.async coordinates ----
    const __half* wbS[4];
    uint32_t wsoff[4];
    #pragma unroll
    for (int j = 0; j < 4; j++) {
        int wi = j * 256 + tid;
        int row = wi >> 2, cg = wi & 3;
        wsoff[j] = SWZ64A((uint32_t)(row * 64 + cg * 16));
        int isq = (row < 128);
        int rl  = row & 127;
        wbS[j] = (isq ? g_Wq : g_Wk) + (size_t)(g * 128 + rl) * FIN + cg * 8;
    }
    uint32_t xsoff[2];
    int xrr[2], xsg[2];
    #pragma unroll
    for (int j = 0; j < 2; j++) {
        int xi = j * 256 + tid;
        xrr[j] = xi >> 4; xsg[j] = xi & 15;
        xsoff[j] = SWZ256((uint32_t)(xrr[j] * 256 + xsg[j] * 16));
    }

    float creg[4][8][4];
    #pragma unroll
    for (int a = 0; a < 4; a++)
        #pragma unroll
        for (int n = 0; n < 8; n++)
            #pragma unroll
            for (int j = 0; j < 4; j++) creg[a][n][j] = 0.f;

    // prologue: issue chunks 0 and 1 into buffers 0,1
    #pragma unroll
    for (int j = 0; j < 4; j++)
        cpa16(sbase + BW_S + wsoff[j], wbS[j]);
    #pragma unroll
    for (int j = 0; j < 2; j++)
        cpa16(sbase + BX_S + xsoff[j], xbh + xrr[j] * SEQ + xsg[j] * 8);
    CP_COMMIT();
    {
        const uint32_t nb = sbase + BUF_SZ;
        #pragma unroll
        for (int j = 0; j < 4; j++)
            cpa16(nb + BW_S + wsoff[j], wbS[j] + CH);
        #pragma unroll
        for (int j = 0; j < 2; j++)
            cpa16(nb + BX_S + xsoff[j], xbh + (size_t)(CH + xrr[j]) * SEQ + xsg[j] * 8);
        CP_COMMIT();
    }

    // ================= fused Q+K projection mainloop (1 fp16 term) =============
    int bufIdx = 0;
    #pragma unroll 1
    for (int kc = 0; kc < NC; kc++) {
        if (kc < NC - 1) { CP_WAIT1(); } else { CP_WAIT0(); }
        __syncthreads();

        if (kc + 2 < NC) {
            int nIdx = bufIdx + 2; if (nIdx >= 3) nIdx -= 3;
            const uint32_t nb = sbase + nIdx * BUF_SZ;
            const int kn = (kc + 2) * CH;
            #pragma unroll
            for (int j = 0; j < 4; j++)
                cpa16(nb + BW_S + wsoff[j], wbS[j] + kn);
            #pragma unroll
            for (int j = 0; j < 2; j++)
                cpa16(nb + BX_S + xsoff[j], xbh + (size_t)(kn + xrr[j]) * SEQ + xsg[j] * 8);
            CP_COMMIT();
        }

        const uint32_t bufb = sbase + bufIdx * BUF_SZ;
        #pragma unroll
        for (int ks = 0; ks < 2; ks++) {
            const int k0 = ks * 16;
            uint32_t aS[4][4];
            #pragma unroll
            for (int mt = 0; mt < 4; mt++) {
                int row = m0 + mt * 16 + (lid & 15);
                int col = k0 + ((lid >> 4) << 3);
                uint32_t off = SWZ64A((uint32_t)(row * 64 + col * 2));
                ldsm4(aS[mt], bufb + BW_S + off);
            }
            const int tL  = lid >> 3;
            const int krw = k0 + ((tL & 1) << 3) + (lid & 7);
            uint32_t bCur[4], bNxt[4];
            {
                int nc = n0 + ((tL >> 1) << 3);
                ldsm4t(bCur, bufb + BX_S + SWZ256((uint32_t)(krw * 256 + nc * 2)));
            }
            #pragma unroll
            for (int np = 0; np < 4; np++) {
                if (np < 3) {
                    int nc = n0 + (np + 1) * 16 + ((tL >> 1) << 3);
                    ldsm4t(bNxt, bufb + BX_S + SWZ256((uint32_t)(krw * 256 + nc * 2)));
                }
                #pragma unroll
                for (int mt = 0; mt < 4; mt++) mma16816(creg[mt][np * 2],     aS[mt], bCur[0], bCur[1]);
                #pragma unroll
                for (int mt = 0; mt < 4; mt++) mma16816(creg[mt][np * 2 + 1], aS[mt], bCur[2], bCur[3]);
                #pragma unroll
                for (int j = 0; j < 4; j++) bCur[j] = bNxt[j];
            }
        }
        if (++bufIdx == 3) bufIdx = 0;
    }
    __syncthreads();   // all buffer reads done before KT_L overlay writes

    // ---- writeback: stacked C -> qT / kT split fp16 (+bias; q scaled 1/8) ----
    {
        #pragma unroll
        for (int mt = 0; mt < 4; mt++)
            #pragma unroll
            for (int rj = 0; rj < 2; rj++) {
                int m = m0 + mt * 16 + rj * 8 + gq;
                int isq = (m < 128);
                int mloc = m & 127;
                float bias = isq ? bqs[mloc] : bks[mloc];
                int head = mloc >> 6, d = mloc & 63;
                char* dh = smem + (isq ? QT_H : KT_H) + head * 16384;
                char* dl = smem + (isq ? QT_L : KT_L) + head * 16384;
                #pragma unroll
                for (int nt = 0; nt < 8; nt++)
                    #pragma unroll
                    for (int jj = 0; jj < 2; jj++) {
                        int n = n0 + nt * 8 + tq * 2 + jj;
                        float v = creg[mt][nt][rj * 2 + jj] + bias;
                        if (isq) v *= 0.125f;
                        __half h = __float2half_rn(v);
                        __half l = __float2half_rn(v - __half2float(h));
                        uint32_t off = SWZ128((uint32_t)(n * 128 + d * 2));
                        *(__half*)(dh + off) = h;
                        *(__half*)(dl + off) = l;
                    }
            }
    }
    __syncthreads();

    // ================= Phase 2: scores (3-term fp16) + softmax + w reduction ====
    {
        const int head = w >> 2;
        const int sb0  = (w & 3) * 32;
        const uint32_t qh = sbase + QT_H + head * 16384;
        const uint32_t ql = sbase + QT_L + head * 16384;
        const uint32_t kh = sbase + KT_H + head * 16384;
        const uint32_t kl = sbase + KT_L + head * 16384;

        float wacc[16][2];
        #pragma unroll
        for (int nt = 0; nt < 16; nt++) { wacc[nt][0] = 0.f; wacc[nt][1] = 0.f; }

        #pragma unroll 1
        for (int chunk = 0; chunk < 2; chunk++) {
            const int s0 = sb0 + chunk * 16;
            float sc[16][4];
            #pragma unroll
            for (int nt = 0; nt < 16; nt++)
                #pragma unroll
                for (int j = 0; j < 4; j++) sc[nt][j] = 0.f;

            #pragma unroll
            for (int ks = 0; ks < 4; ks++) {
                const int k0 = ks * 16;
                uint32_t aH[4], aL[4];
                {
                    int row = s0 + (lid & 15);
                    int col = k0 + ((lid >> 4) << 3);
                    uint32_t off = SWZ128((uint32_t)(row * 128 + col * 2));
                    ldsm4(aH, qh + off);
                    ldsm4(aL, ql + off);
                }
                #pragma unroll
                for (int npp = 0; npp < 4; npp++) {
                    int tL = lid >> 3;
                    int ccol = k0 + ((tL & 1) << 3);
                    int r0 = (npp * 2) * 16 + ((tL >> 1) << 3) + (lid & 7);
                    int r1 = (npp * 2 + 1) * 16 + ((tL >> 1) << 3) + (lid & 7);
                    uint32_t bH0[4], bL0[4], bH1[4], bL1[4];
                    ldsm4(bH0, kh + SWZ128((uint32_t)(r0 * 128 + ccol * 2)));
                    ldsm4(bL0, kl + SWZ128((uint32_t)(r0 * 128 + ccol * 2)));
                    ldsm4(bH1, kh + SWZ128((uint32_t)(r1 * 128 + ccol * 2)));
                    ldsm4(bL1, kl + SWZ128((uint32_t)(r1 * 128 + ccol * 2)));
                    float* s00 = sc[npp * 4 + 0];
                    float* s01 = sc[npp * 4 + 1];
                    float* s10 = sc[npp * 4 + 2];
                    float* s11 = sc[npp * 4 + 3];
                    mma16816(s00, aH, bH0[0], bH0[1]);
                    mma16816(s01, aH, bH0[2], bH0[3]);
                    mma16816(s10, aH, bH1[0], bH1[1]);
                    mma16816(s11, aH, bH1[2], bH1[3]);
                    mma16816(s00, aH, bL0[0], bL0[1]);
                    mma16816(s01, aH, bL0[2], bL0[3]);
                    mma16816(s10, aH, bL1[0], bL1[1]);
                    mma16816(s11, aH, bL1[2], bL1[3]);
                    mma16816(s00, aL, bH0[0], bH0[1]);
                    mma16816(s01, aL, bH0[2], bH0[3]);
                    mma16816(s10, aL, bH1[0], bH1[1]);
                    mma16816(s11, aL, bH1[2], bH1[3]);
                }
            }
            float mx0 = -1e30f, mx1 = -1e30f;
            #pragma unroll
            for (int nt = 0; nt < 16; nt++) {
                mx0 = fmaxf(mx0, fmaxf(sc[nt][0], sc[nt][1]));
                mx1 = fmaxf(mx1, fmaxf(sc[nt][2], sc[nt][3]));
            }
            mx0 = fmaxf(mx0, __shfl_xor_sync(0xffffffffu, mx0, 1));
            mx0 = fmaxf(mx0, __shfl_xor_sync(0xffffffffu, mx0, 2));
            mx1 = fmaxf(mx1, __shfl_xor_sync(0xffffffffu, mx1, 1));
            mx1 = fmaxf(mx1, __shfl_xor_sync(0xffffffffu, mx1, 2));
            float Z0 = 0.f, Z1 = 0.f;
            #pragma unroll
            for (int nt = 0; nt < 16; nt++) {
                sc[nt][0] = __expf(sc[nt][0] - mx0); Z0 += sc[nt][0];
                sc[nt][1] = __expf(sc[nt][1] - mx0); Z0 += sc[nt][1];
                sc[nt][2] = __expf(sc[nt][2] - mx1); Z1 += sc[nt][2];
                sc[nt][3] = __expf(sc[nt][3] - mx1); Z1 += sc[nt][3];
            }
            Z0 += __shfl_xor_sync(0xffffffffu, Z0, 1);
            Z0 += __shfl_xor_sync(0xffffffffu, Z0, 2);
            Z1 += __shfl_xor_sync(0xffffffffu, Z1, 1);
            Z1 += __shfl_xor_sync(0xffffffffu, Z1, 2);
            const float c0 = wos[s0 + gq]     / Z0;
            const float c1 = wos[s0 + 8 + gq] / Z1;
            #pragma unroll
            for (int nt = 0; nt < 16; nt++) {
                wacc[nt][0] += sc[nt][0] * c0 + sc[nt][2] * c1;
                wacc[nt][1] += sc[nt][1] * c0 + sc[nt][3] * c1;
            }
        }
        #pragma unroll
        for (int d = 4; d < 32; d <<= 1)
            #pragma unroll
            for (int nt = 0; nt < 16; nt++) {
                wacc[nt][0] += __shfl_xor_sync(0xffffffffu, wacc[nt][0], d);
                wacc[nt][1] += __shfl_xor_sync(0xffffffffu, wacc[nt][1], d);
            }
        if (lid < 4) {
            #pragma unroll
            for (int nt = 0; nt < 16; nt++) {
                atomicAdd(&wsm[head * 128 + nt * 8 + 2 * lid],     wacc[nt][0]);
                atomicAdd(&wsm[head * 128 + nt * 8 + 2 * lid + 1], wacc[nt][1]);
            }
        }
    }
    __syncthreads();

    // ================= Phase 3: out[b, g*128+f] = sum_t w[head][t]*x[b,f,t] + bo
    if (tid < 128) {
        const float* wv2 = wsm + (tid >> 6) * 128;
        const float4* x4 = (const float4*)(xb + (size_t)(g * 128 + tid) * SEQ);
        float acc = 0.f;
        #pragma unroll 8
        for (int t4 = 0; t4 < 32; t4++) {
            float4 xvv = x4[t4];
            acc += xvv.x * wv2[t4 * 4 + 0] + xvv.y * wv2[t4 * 4 + 1]
                 + xvv.z * wv2[t4 * 4 + 2] + xvv.w * wv2[t4 * 4 + 3];
        }
        out[(size_t)b * FIN + g * 128 + tid] = acc + bo[0];
    }
}

extern "C" void kernel_launch(void* const* d_in, const int* in_sizes, int n_in,
                              void* d_out, int out_size)
{
    (void)in_sizes; (void)n_in; (void)out_size;
    const float* x  = (const float*)d_in[0];
    const float* Wq = (const float*)d_in[1];
    const float* bq = (const float*)d_in[2];
    const float* Wk = (const float*)d_in[3];
    const float* bk = (const float*)d_in[4];
    const float* Wo = (const float*)d_in[5];
    const float* bo = (const float*)d_in[6];
    float* out = (float*)d_out;

    prep_w_kernel<<<1024, 256>>>(Wq, Wk);
    prep_x_kernel<<<32768, 256>>>(x);

    cudaFuncSetAttribute(Attention_75402445849133_kernel,
                         cudaFuncAttributeMaxDynamicSharedMemorySize, SMEM_TOTAL);
    dim3 grid(8, 256, 1);
    Attention_75402445849133_kernel<<<grid, 256, SMEM_TOTAL>>>(x, bq, bk, Wo, bo, out);
}

// round 12
// speedup vs baseline: 1.5850x; 1.0765x over previous
#include <cuda_runtime.h>
#include <cuda_fp16.h>
#include <cstdint>

// ============ sm_103-safe primitives ============
__device__ __forceinline__ uint32_t smem_u32(const void* p) {
    uint32_t a;
    asm("{ .reg .u64 t; cvta.to.shared.u64 t, %1; cvt.u32.u64 %0, t; }" : "=r"(a) : "l"(p));
    return a;
}
__device__ __forceinline__ void ldsm4(uint32_t r[4], uint32_t addr) {
    asm volatile("ldmatrix.sync.aligned.m8n8.x4.shared.b16 {%0,%1,%2,%3}, [%4];"
                 : "=r"(r[0]), "=r"(r[1]), "=r"(r[2]), "=r"(r[3]) : "r"(addr));
}
__device__ __forceinline__ void ldsm4t(uint32_t r[4], uint32_t addr) {
    asm volatile("ldmatrix.sync.aligned.m8n8.x4.trans.shared.b16 {%0,%1,%2,%3}, [%4];"
                 : "=r"(r[0]), "=r"(r[1]), "=r"(r[2]), "=r"(r[3]) : "r"(addr));
}
__device__ __forceinline__ void mma16816(float c[4], const uint32_t a[4],
                                         uint32_t b0, uint32_t b1) {
    asm volatile(
        "mma.sync.aligned.m16n8k16.row.col.f32.f16.f16.f32 "
        "{%0,%1,%2,%3},{%4,%5,%6,%7},{%8,%9},{%0,%1,%2,%3};"
        : "+f"(c[0]), "+f"(c[1]), "+f"(c[2]), "+f"(c[3])
        : "r"(a[0]), "r"(a[1]), "r"(a[2]), "r"(a[3]), "r"(b0), "r"(b1));
}
__device__ __forceinline__ uint32_t pack2h(__half lo, __half hi) {
    return ((uint32_t)__half_as_ushort(hi) << 16) | (uint32_t)__half_as_ushort(lo);
}
__device__ __forceinline__ uint2 cvt4h(float4 v) {
    return make_uint2(pack2h(__float2half_rn(v.x), __float2half_rn(v.y)),
                      pack2h(__float2half_rn(v.z), __float2half_rn(v.w)));
}
__device__ __forceinline__ void cpa16(uint32_t dst, const void* src) {
    asm volatile("cp.async.cg.shared.global [%0], [%1], 16;" :: "r"(dst), "l"(src) : "memory");
}
#define CP_COMMIT() asm volatile("cp.async.commit_group;" ::: "memory")
#define CP_WAIT1()  asm volatile("cp.async.wait_group 1;" ::: "memory")
#define CP_WAIT0()  asm volatile("cp.async.wait_group 0;" ::: "memory")
#define SWZ64A(o) ((o) ^ (((o) >> 2) & 0x70))
#define SWZ128(o) ((o) ^ (((o) >> 3) & 0x70))
#define SWZ256(o) ((o) ^ (((o) >> 4) & 0x70))

// ============ problem constants ============
#define FIN  1024
#define SEQ  128
#define CH   32
#define NC   32

// ============ pre-converted global staging (single fp16) ============
__device__ __align__(16) __half g_Wq[1024 * 1024];
__device__ __align__(16) __half g_Wk[1024 * 1024];
__device__ __align__(16) __half g_x[256 * 1024 * 128];

__global__ void __launch_bounds__(256) prep_w_kernel(const float* __restrict__ Wq,
                                                     const float* __restrict__ Wk) {
    int i = blockIdx.x * 256 + threadIdx.x;
    ((uint2*)g_Wq)[i] = cvt4h(((const float4*)Wq)[i]);
    ((uint2*)g_Wk)[i] = cvt4h(((const float4*)Wk)[i]);
}
__global__ void __launch_bounds__(256) prep_x_kernel(const float* __restrict__ x) {
    size_t i = (size_t)blockIdx.x * 256 + threadIdx.x;
    ((uint2*)g_x)[i] = cvt4h(((const float4*)x)[i]);
}

// ============ SMEM layout (bytes) ============
// 3-stage chunk buffers: [W 256x32 fp16 16K | x 32x128 fp16 8K] x 3 = 72K
#define BUF_SZ  24576
#define BW_S    0
#define BX_S    16384
#define QT_S    73728          // 2 heads x [128 s][64 d] fp16 (16K/head)
#define KT_S    106496
#define W_SM    139264
#define BQ_SM   140288
#define BK_SM   140800
#define WO_SM   141312
#define SMEM_TOTAL 141824

__global__ void __launch_bounds__(256, 1)
Attention_75402445849133_kernel(const float* __restrict__ x,
                                const float* __restrict__ bq, const float* __restrict__ bk,
                                const float* __restrict__ Wo, const float* __restrict__ bo,
                                float* __restrict__ out)
{
    extern __shared__ char smem[];
    const uint32_t sbase = smem_u32(smem);
    const int tid = threadIdx.x;
    const int w   = tid >> 5;
    const int lid = tid & 31;
    const int gq  = lid >> 2;
    const int tq  = lid & 3;
    const int g   = blockIdx.x;
    const int b   = blockIdx.y;

    float* wsm = (float*)(smem + W_SM);
    float* bqs = (float*)(smem + BQ_SM);
    float* bks = (float*)(smem + BK_SM);
    float* wos = (float*)(smem + WO_SM);
    if (tid < 128) {
        bqs[tid] = bq[g * 128 + tid];
        bks[tid] = bk[g * 128 + tid];
        wos[tid] = Wo[tid];
    }
    wsm[tid] = 0.0f;

    const float* xb = x + (size_t)b * FIN * SEQ;
    const __half* xbh = g_x + (size_t)b * FIN * SEQ;

    const int m0 = (w & 3) * 64;
    const int n0 = (w >> 2) * 64;

    // ---- cp.async coordinates ----
    const __half* wbS[4];
    uint32_t wsoff[4];
    #pragma unroll
    for (int j = 0; j < 4; j++) {
        int wi = j * 256 + tid;
        int row = wi >> 2, cg = wi & 3;
        wsoff[j] = SWZ64A((uint32_t)(row * 64 + cg * 16));
        int isq = (row < 128);
        int rl  = row & 127;
        wbS[j] = (isq ? g_Wq : g_Wk) + (size_t)(g * 128 + rl) * FIN + cg * 8;
    }
    uint32_t xsoff[2];
    int xrr[2], xsg[2];
    #pragma unroll
    for (int j = 0; j < 2; j++) {
        int xi = j * 256 + tid;
        xrr[j] = xi >> 4; xsg[j] = xi & 15;
        xsoff[j] = SWZ256((uint32_t)(xrr[j] * 256 + xsg[j] * 16));
    }

    float creg[4][8][4];
    #pragma unroll
    for (int a = 0; a < 4; a++)
        #pragma unroll
        for (int n = 0; n < 8; n++)
            #pragma unroll
            for (int j = 0; j < 4; j++) creg[a][n][j] = 0.f;

    // prologue: issue chunks 0 and 1 into buffers 0,1
    #pragma unroll
    for (int j = 0; j < 4; j++)
        cpa16(sbase + BW_S + wsoff[j], wbS[j]);
    #pragma unroll
    for (int j = 0; j < 2; j++)
        cpa16(sbase + BX_S + xsoff[j], xbh + xrr[j] * SEQ + xsg[j] * 8);
    CP_COMMIT();
    {
        const uint32_t nb = sbase + BUF_SZ;
        #pragma unroll
        for (int j = 0; j < 4; j++)
            cpa16(nb + BW_S + wsoff[j], wbS[j] + CH);
        #pragma unroll
        for (int j = 0; j < 2; j++)
            cpa16(nb + BX_S + xsoff[j], xbh + (size_t)(CH + xrr[j]) * SEQ + xsg[j] * 8);
        CP_COMMIT();
    }

    // ================= fused Q+K projection mainloop (1 fp16 term) =============
    int bufIdx = 0;
    #pragma unroll 1
    for (int kc = 0; kc < NC; kc++) {
        if (kc < NC - 1) { CP_WAIT1(); } else { CP_WAIT0(); }
        __syncthreads();

        if (kc + 2 < NC) {
            int nIdx = bufIdx + 2; if (nIdx >= 3) nIdx -= 3;
            const uint32_t nb = sbase + nIdx * BUF_SZ;
            const int kn = (kc + 2) * CH;
            #pragma unroll
            for (int j = 0; j < 4; j++)
                cpa16(nb + BW_S + wsoff[j], wbS[j] + kn);
            #pragma unroll
            for (int j = 0; j < 2; j++)
                cpa16(nb + BX_S + xsoff[j], xbh + (size_t)(kn + xrr[j]) * SEQ + xsg[j] * 8);
            CP_COMMIT();
        }

        const uint32_t bufb = sbase + bufIdx * BUF_SZ;
        #pragma unroll
        for (int ks = 0; ks < 2; ks++) {
            const int k0 = ks * 16;
            uint32_t aS[4][4];
            #pragma unroll
            for (int mt = 0; mt < 4; mt++) {
                int row = m0 + mt * 16 + (lid & 15);
                int col = k0 + ((lid >> 4) << 3);
                uint32_t off = SWZ64A((uint32_t)(row * 64 + col * 2));
                ldsm4(aS[mt], bufb + BW_S + off);
            }
            const int tL  = lid >> 3;
            const int krw = k0 + ((tL & 1) << 3) + (lid & 7);
            uint32_t bCur[4], bNxt[4];
            {
                int nc = n0 + ((tL >> 1) << 3);
                ldsm4t(bCur, bufb + BX_S + SWZ256((uint32_t)(krw * 256 + nc * 2)));
            }
            #pragma unroll
            for (int np = 0; np < 4; np++) {
                if (np < 3) {
                    int nc = n0 + (np + 1) * 16 + ((tL >> 1) << 3);
                    ldsm4t(bNxt, bufb + BX_S + SWZ256((uint32_t)(krw * 256 + nc * 2)));
                }
                #pragma unroll
                for (int mt = 0; mt < 4; mt++) mma16816(creg[mt][np * 2],     aS[mt], bCur[0], bCur[1]);
                #pragma unroll
                for (int mt = 0; mt < 4; mt++) mma16816(creg[mt][np * 2 + 1], aS[mt], bCur[2], bCur[3]);
                #pragma unroll
                for (int j = 0; j < 4; j++) bCur[j] = bNxt[j];
            }
        }
        if (++bufIdx == 3) bufIdx = 0;
    }

    // ---- writeback: stacked C -> qT / kT single fp16 (+bias; q scaled 1/8) ----
    {
        #pragma unroll
        for (int mt = 0; mt < 4; mt++)
            #pragma unroll
            for (int rj = 0; rj < 2; rj++) {
                int m = m0 + mt * 16 + rj * 8 + gq;
                int isq = (m < 128);
                int mloc = m & 127;
                float bias = isq ? bqs[mloc] : bks[mloc];
                int head = mloc >> 6, d = mloc & 63;
                char* dh = smem + (isq ? QT_S : KT_S) + head * 16384;
                #pragma unroll
                for (int nt = 0; nt < 8; nt++)
                    #pragma unroll
                    for (int jj = 0; jj < 2; jj++) {
                        int n = n0 + nt * 8 + tq * 2 + jj;
                        float v = creg[mt][nt][rj * 2 + jj] + bias;
                        if (isq) v *= 0.125f;
                        uint32_t off = SWZ128((uint32_t)(n * 128 + d * 2));
                        *(__half*)(dh + off) = __float2half_rn(v);
                    }
            }
    }
    __syncthreads();

    // ================= Phase 2: scores (single fp16) + softmax + w reduction ====
    {
        const int head = w >> 2;
        const int sb0  = (w & 3) * 32;
        const uint32_t qh = sbase + QT_S + head * 16384;
        const uint32_t kh = sbase + KT_S + head * 16384;

        float wacc[16][2];
        #pragma unroll
        for (int nt = 0; nt < 16; nt++) { wacc[nt][0] = 0.f; wacc[nt][1] = 0.f; }

        #pragma unroll 1
        for (int chunk = 0; chunk < 2; chunk++) {
            const int s0 = sb0 + chunk * 16;
            float sc[16][4];
            #pragma unroll
            for (int nt = 0; nt < 16; nt++)
                #pragma unroll
                for (int j = 0; j < 4; j++) sc[nt][j] = 0.f;

            #pragma unroll
            for (int ks = 0; ks < 4; ks++) {
                const int k0 = ks * 16;
                uint32_t aS[4];
                {
                    int row = s0 + (lid & 15);
                    int col = k0 + ((lid >> 4) << 3);
                    uint32_t off = SWZ128((uint32_t)(row * 128 + col * 2));
                    ldsm4(aS, qh + off);
                }
                #pragma unroll
                for (int npp = 0; npp < 4; npp++) {
                    int tL = lid >> 3;
                    int ccol = k0 + ((tL & 1) << 3);
                    int r0 = (npp * 2) * 16 + ((tL >> 1) << 3) + (lid & 7);
                    int r1 = (npp * 2 + 1) * 16 + ((tL >> 1) << 3) + (lid & 7);
                    uint32_t bH0[4], bH1[4];
                    ldsm4(bH0, kh + SWZ128((uint32_t)(r0 * 128 + ccol * 2)));
                    ldsm4(bH1, kh + SWZ128((uint32_t)(r1 * 128 + ccol * 2)));
                    mma16816(sc[npp * 4 + 0], aS, bH0[0], bH0[1]);
                    mma16816(sc[npp * 4 + 1], aS, bH0[2], bH0[3]);
                    mma16816(sc[npp * 4 + 2], aS, bH1[0], bH1[1]);
                    mma16816(sc[npp * 4 + 3], aS, bH1[2], bH1[3]);
                }
            }
            float mx0 = -1e30f, mx1 = -1e30f;
            #pragma unroll
            for (int nt = 0; nt < 16; nt++) {
                mx0 = fmaxf(mx0, fmaxf(sc[nt][0], sc[nt][1]));
                mx1 = fmaxf(mx1, fmaxf(sc[nt][2], sc[nt][3]));
            }
            mx0 = fmaxf(mx0, __shfl_xor_sync(0xffffffffu, mx0, 1));
            mx0 = fmaxf(mx0, __shfl_xor_sync(0xffffffffu, mx0, 2));
            mx1 = fmaxf(mx1, __shfl_xor_sync(0xffffffffu, mx1, 1));
            mx1 = fmaxf(mx1, __shfl_xor_sync(0xffffffffu, mx1, 2));
            float Z0 = 0.f, Z1 = 0.f;
            #pragma unroll
            for (int nt = 0; nt < 16; nt++) {
                sc[nt][0] = __expf(sc[nt][0] - mx0); Z0 += sc[nt][0];
                sc[nt][1] = __expf(sc[nt][1] - mx0); Z0 += sc[nt][1];
                sc[nt][2] = __expf(sc[nt][2] - mx1); Z1 += sc[nt][2];
                sc[nt][3] = __expf(sc[nt][3] - mx1); Z1 += sc[nt][3];
            }
            Z0 += __shfl_xor_sync(0xffffffffu, Z0, 1);
            Z0 += __shfl_xor_sync(0xffffffffu, Z0, 2);
            Z1 += __shfl_xor_sync(0xffffffffu, Z1, 1);
            Z1 += __shfl_xor_sync(0xffffffffu, Z1, 2);
            const float c0 = wos[s0 + gq]     / Z0;
            const float c1 = wos[s0 + 8 + gq] / Z1;
            #pragma unroll
            for (int nt = 0; nt < 16; nt++) {
                wacc[nt][0] += sc[nt][0] * c0 + sc[nt][2] * c1;
                wacc[nt][1] += sc[nt][1] * c0 + sc[nt][3] * c1;
            }
        }
        #pragma unroll
        for (int d = 4; d < 32; d <<= 1)
            #pragma unroll
            for (int nt = 0; nt < 16; nt++) {
                wacc[nt][0] += __shfl_xor_sync(0xffffffffu, wacc[nt][0], d);
                wacc[nt][1] += __shfl_xor_sync(0xffffffffu, wacc[nt][1], d);
            }
        if (lid < 4) {
            #pragma unroll
            for (int nt = 0; nt < 16; nt++) {
                atomicAdd(&wsm[head * 128 + nt * 8 + 2 * lid],     wacc[nt][0]);
                atomicAdd(&wsm[head * 128 + nt * 8 + 2 * lid + 1], wacc[nt][1]);
            }
        }
    }
    __syncthreads();

    // ================= Phase 3: out[b, g*128+f] = sum_t w[head][t]*x[b,f,t] + bo
    if (tid < 128) {
        const float* wv2 = wsm + (tid >> 6) * 128;
        const float4* x4 = (const float4*)(xb + (size_t)(g * 128 + tid) * SEQ);
        float acc = 0.f;
        #pragma unroll 8
        for (int t4 = 0; t4 < 32; t4++) {
            float4 xvv = x4[t4];
            acc += xvv.x * wv2[t4 * 4 + 0] + xvv.y * wv2[t4 * 4 + 1]
                 + xvv.z * wv2[t4 * 4 + 2] + xvv.w * wv2[t4 * 4 + 3];
        }
        out[(size_t)b * FIN + g * 128 + tid] = acc + bo[0];
    }
}

extern "C" void kernel_launch(void* const* d_in, const int* in_sizes, int n_in,
                              void* d_out, int out_size)
{
    (void)in_sizes; (void)n_in; (void)out_size;
    const float* x  = (const float*)d_in[0];
    const float* Wq = (const float*)d_in[1];
    const float* bq = (const float*)d_in[2];
    const float* Wk = (const float*)d_in[3];
    const float* bk = (const float*)d_in[4];
    const float* Wo = (const float*)d_in[5];
    const float* bo = (const float*)d_in[6];
    float* out = (float*)d_out;

    prep_w_kernel<<<1024, 256>>>(Wq, Wk);
    prep_x_kernel<<<32768, 256>>>(x);

    cudaFuncSetAttribute(Attention_75402445849133_kernel,
                         cudaFuncAttributeMaxDynamicSharedMemorySize, SMEM_TOTAL);
    dim3 grid(8, 256, 1);
    Attention_75402445849133_kernel<<<grid, 256, SMEM_TOTAL>>>(x, bq, bk, Wo, bo, out);
}

// round 13
// speedup vs baseline: 1.8978x; 1.1973x over previous
#include <cuda_runtime.h>
#include <cuda_fp16.h>
#include <cstdint>

// ============ sm_103-safe primitives ============
__device__ __forceinline__ uint32_t smem_u32(const void* p) {
    uint32_t a;
    asm("{ .reg .u64 t; cvta.to.shared.u64 t, %1; cvt.u32.u64 %0, t; }" : "=r"(a) : "l"(p));
    return a;
}
__device__ __forceinline__ void ldsm4(uint32_t r[4], uint32_t addr) {
    asm volatile("ldmatrix.sync.aligned.m8n8.x4.shared.b16 {%0,%1,%2,%3}, [%4];"
                 : "=r"(r[0]), "=r"(r[1]), "=r"(r[2]), "=r"(r[3]) : "r"(addr));
}
__device__ __forceinline__ void ldsm4t(uint32_t r[4], uint32_t addr) {
    asm volatile("ldmatrix.sync.aligned.m8n8.x4.trans.shared.b16 {%0,%1,%2,%3}, [%4];"
                 : "=r"(r[0]), "=r"(r[1]), "=r"(r[2]), "=r"(r[3]) : "r"(addr));
}
__device__ __forceinline__ void mma16816(float c[4], const uint32_t a[4],
                                         uint32_t b0, uint32_t b1) {
    asm volatile(
        "mma.sync.aligned.m16n8k16.row.col.f32.f16.f16.f32 "
        "{%0,%1,%2,%3},{%4,%5,%6,%7},{%8,%9},{%0,%1,%2,%3};"
        : "+f"(c[0]), "+f"(c[1]), "+f"(c[2]), "+f"(c[3])
        : "r"(a[0]), "r"(a[1]), "r"(a[2]), "r"(a[3]), "r"(b0), "r"(b1));
}
__device__ __forceinline__ uint32_t pack2h(__half lo, __half hi) {
    return ((uint32_t)__half_as_ushort(hi) << 16) | (uint32_t)__half_as_ushort(lo);
}
__device__ __forceinline__ uint2 cvt4h(float4 v) {
    return make_uint2(pack2h(__float2half_rn(v.x), __float2half_rn(v.y)),
                      pack2h(__float2half_rn(v.z), __float2half_rn(v.w)));
}
__device__ __forceinline__ void cpa16(uint32_t dst, const void* src) {
    asm volatile("cp.async.cg.shared.global [%0], [%1], 16;" :: "r"(dst), "l"(src) : "memory");
}
#define CP_COMMIT() asm volatile("cp.async.commit_group;" ::: "memory")
#define CP_WAIT1()  asm volatile("cp.async.wait_group 1;" ::: "memory")
#define CP_WAIT0()  asm volatile("cp.async.wait_group 0;" ::: "memory")
#define SWZ128(o) ((o) ^ (((o) >> 3) & 0x70))
#define SWZ256(o) ((o) ^ (((o) >> 4) & 0x70))

// ============ problem constants ============
#define FIN  1024
#define SEQ  128
#define CH   64            // K per chunk
#define NC   16            // chunks

// ============ pre-converted global staging (single fp16) ============
__device__ __align__(16) __half g_Wq[1024 * 1024];
__device__ __align__(16) __half g_Wk[1024 * 1024];
__device__ __align__(16) __half g_x[256 * 1024 * 128];

__global__ void __launch_bounds__(256) prep_w_kernel(const float* __restrict__ Wq,
                                                     const float* __restrict__ Wk) {
    int i = blockIdx.x * 256 + threadIdx.x;
    ((uint2*)g_Wq)[i] = cvt4h(((const float4*)Wq)[i]);
    ((uint2*)g_Wk)[i] = cvt4h(((const float4*)Wk)[i]);
}
__global__ void __launch_bounds__(256) prep_x_kernel(const float* __restrict__ x) {
    size_t i = (size_t)blockIdx.x * 256 + threadIdx.x;
    ((uint2*)g_x)[i] = cvt4h(((const float4*)x)[i]);
}

// ============ SMEM layout (bytes) ============
// 3-stage chunk buffers: [W 256x64 fp16 32K | x 64x128 fp16 16K] x 3 = 144K
#define BUF_SZ  49152
#define BW_S    0
#define BX_S    32768
#define QT_S    147456         // 2 heads x [128 s][64 d] fp16 (16K/head)
#define KT_S    180224
#define W_SM    212992
#define BQ_SM   214016
#define BK_SM   214528
#define WO_SM   215040
#define SMEM_TOTAL 215552

__global__ void __launch_bounds__(256, 1)
Attention_75402445849133_kernel(const float* __restrict__ bq, const float* __restrict__ bk,
                                const float* __restrict__ Wo, const float* __restrict__ bo,
                                float* __restrict__ out)
{
    extern __shared__ char smem[];
    const uint32_t sbase = smem_u32(smem);
    const int tid = threadIdx.x;
    const int w   = tid >> 5;
    const int lid = tid & 31;
    const int gq  = lid >> 2;
    const int tq  = lid & 3;
    const int g   = blockIdx.x;
    const int b   = blockIdx.y;

    float* wsm = (float*)(smem + W_SM);
    float* bqs = (float*)(smem + BQ_SM);
    float* bks = (float*)(smem + BK_SM);
    float* wos = (float*)(smem + WO_SM);
    if (tid < 128) {
        bqs[tid] = bq[g * 128 + tid];
        bks[tid] = bk[g * 128 + tid];
        wos[tid] = Wo[tid];
    }
    wsm[tid] = 0.0f;

    const __half* xbh = g_x + (size_t)b * FIN * SEQ;

    const int m0 = (w & 3) * 64;
    const int n0 = (w >> 2) * 64;

    // ---- cp.async coordinates ----
    // W chunk: 256 rows x 64 fp16 (128B/row) = 2048 granules; 8 per thread
    const __half* wbS[8];
    uint32_t wsoff[8];
    #pragma unroll
    for (int j = 0; j < 8; j++) {
        int wi = j * 256 + tid;
        int row = wi >> 3, cg = wi & 7;
        wsoff[j] = SWZ128((uint32_t)(row * 128 + cg * 16));
        int isq = (row < 128);
        int rl  = row & 127;
        wbS[j] = (isq ? g_Wq : g_Wk) + (size_t)(g * 128 + rl) * FIN + cg * 8;
    }
    // x chunk: 64 rows x 128 fp16 (256B/row) = 1024 granules; 4 per thread
    uint32_t xsoff[4];
    int xrr[4], xsg[4];
    #pragma unroll
    for (int j = 0; j < 4; j++) {
        int xi = j * 256 + tid;
        xrr[j] = xi >> 4; xsg[j] = xi & 15;
        xsoff[j] = SWZ256((uint32_t)(xrr[j] * 256 + xsg[j] * 16));
    }

    float creg[4][8][4];
    #pragma unroll
    for (int a = 0; a < 4; a++)
        #pragma unroll
        for (int n = 0; n < 8; n++)
            #pragma unroll
            for (int j = 0; j < 4; j++) creg[a][n][j] = 0.f;

    // prologue: issue chunks 0 and 1 into buffers 0,1
    #pragma unroll
    for (int j = 0; j < 8; j++)
        cpa16(sbase + BW_S + wsoff[j], wbS[j]);
    #pragma unroll
    for (int j = 0; j < 4; j++)
        cpa16(sbase + BX_S + xsoff[j], xbh + xrr[j] * SEQ + xsg[j] * 8);
    CP_COMMIT();
    {
        const uint32_t nb = sbase + BUF_SZ;
        #pragma unroll
        for (int j = 0; j < 8; j++)
            cpa16(nb + BW_S + wsoff[j], wbS[j] + CH);
        #pragma unroll
        for (int j = 0; j < 4; j++)
            cpa16(nb + BX_S + xsoff[j], xbh + (size_t)(CH + xrr[j]) * SEQ + xsg[j] * 8);
        CP_COMMIT();
    }

    // ================= fused Q+K projection mainloop (1 fp16 term) =============
    int bufIdx = 0;
    #pragma unroll 1
    for (int kc = 0; kc < NC; kc++) {
        if (kc < NC - 1) { CP_WAIT1(); } else { CP_WAIT0(); }
        __syncthreads();

        if (kc + 2 < NC) {
            int nIdx = bufIdx + 2; if (nIdx >= 3) nIdx -= 3;
            const uint32_t nb = sbase + nIdx * BUF_SZ;
            const int kn = (kc + 2) * CH;
            #pragma unroll
            for (int j = 0; j < 8; j++)
                cpa16(nb + BW_S + wsoff[j], wbS[j] + kn);
            #pragma unroll
            for (int j = 0; j < 4; j++)
                cpa16(nb + BX_S + xsoff[j], xbh + (size_t)(kn + xrr[j]) * SEQ + xsg[j] * 8);
            CP_COMMIT();
        }

        const uint32_t bufb = sbase + bufIdx * BUF_SZ;
        #pragma unroll
        for (int ks = 0; ks < 4; ks++) {
            const int k0 = ks * 16;
            uint32_t aS[4][4];
            #pragma unroll
            for (int mt = 0; mt < 4; mt++) {
                int row = m0 + mt * 16 + (lid & 15);
                int col = k0 + ((lid >> 4) << 3);
                uint32_t off = SWZ128((uint32_t)(row * 128 + col * 2));
                ldsm4(aS[mt], bufb + BW_S + off);
            }
            const int tL  = lid >> 3;
            const int krw = k0 + ((tL & 1) << 3) + (lid & 7);
            uint32_t bCur[4], bNxt[4];
            {
                int nc = n0 + ((tL >> 1) << 3);
                ldsm4t(bCur, bufb + BX_S + SWZ256((uint32_t)(krw * 256 + nc * 2)));
            }
            #pragma unroll
            for (int np = 0; np < 4; np++) {
                if (np < 3) {
                    int nc = n0 + (np + 1) * 16 + ((tL >> 1) << 3);
                    ldsm4t(bNxt, bufb + BX_S + SWZ256((uint32_t)(krw * 256 + nc * 2)));
                }
                #pragma unroll
                for (int mt = 0; mt < 4; mt++) mma16816(creg[mt][np * 2],     aS[mt], bCur[0], bCur[1]);
                #pragma unroll
                for (int mt = 0; mt < 4; mt++) mma16816(creg[mt][np * 2 + 1], aS[mt], bCur[2], bCur[3]);
                #pragma unroll
                for (int j = 0; j < 4; j++) bCur[j] = bNxt[j];
            }
        }
        if (++bufIdx == 3) bufIdx = 0;
    }

    // ---- writeback: stacked C -> qT / kT single fp16 (+bias; q scaled 1/8) ----
    {
        #pragma unroll
        for (int mt = 0; mt < 4; mt++)
            #pragma unroll
            for (int rj = 0; rj < 2; rj++) {
                int m = m0 + mt * 16 + rj * 8 + gq;
                int isq = (m < 128);
                int mloc = m & 127;
                float bias = isq ? bqs[mloc] : bks[mloc];
                int head = mloc >> 6, d = mloc & 63;
                char* dh = smem + (isq ? QT_S : KT_S) + head * 16384;
                #pragma unroll
                for (int nt = 0; nt < 8; nt++)
                    #pragma unroll
                    for (int jj = 0; jj < 2; jj++) {
                        int n = n0 + nt * 8 + tq * 2 + jj;
                        float v = creg[mt][nt][rj * 2 + jj] + bias;
                        if (isq) v *= 0.125f;
                        uint32_t off = SWZ128((uint32_t)(n * 128 + d * 2));
                        *(__half*)(dh + off) = __float2half_rn(v);
                    }
            }
    }
    __syncthreads();

    // ================= Phase 2: scores (single fp16) + softmax + w reduction ====
    {
        const int head = w >> 2;
        const int sb0  = (w & 3) * 32;
        const uint32_t qh = sbase + QT_S + head * 16384;
        const uint32_t kh = sbase + KT_S + head * 16384;

        float wacc[16][2];
        #pragma unroll
        for (int nt = 0; nt < 16; nt++) { wacc[nt][0] = 0.f; wacc[nt][1] = 0.f; }

        #pragma unroll 1
        for (int chunk = 0; chunk < 2; chunk++) {
            const int s0 = sb0 + chunk * 16;
            float sc[16][4];
            #pragma unroll
            for (int nt = 0; nt < 16; nt++)
                #pragma unroll
                for (int j = 0; j < 4; j++) sc[nt][j] = 0.f;

            #pragma unroll
            for (int ks = 0; ks < 4; ks++) {
                const int k0 = ks * 16;
                uint32_t aS[4];
                {
                    int row = s0 + (lid & 15);
                    int col = k0 + ((lid >> 4) << 3);
                    uint32_t off = SWZ128((uint32_t)(row * 128 + col * 2));
                    ldsm4(aS, qh + off);
                }
                #pragma unroll
                for (int npp = 0; npp < 4; npp++) {
                    int tL = lid >> 3;
                    int ccol = k0 + ((tL & 1) << 3);
                    int r0 = (npp * 2) * 16 + ((tL >> 1) << 3) + (lid & 7);
                    int r1 = (npp * 2 + 1) * 16 + ((tL >> 1) << 3) + (lid & 7);
                    uint32_t bH0[4], bH1[4];
                    ldsm4(bH0, kh + SWZ128((uint32_t)(r0 * 128 + ccol * 2)));
                    ldsm4(bH1, kh + SWZ128((uint32_t)(r1 * 128 + ccol * 2)));
                    mma16816(sc[npp * 4 + 0], aS, bH0[0], bH0[1]);
                    mma16816(sc[npp * 4 + 1], aS, bH0[2], bH0[3]);
                    mma16816(sc[npp * 4 + 2], aS, bH1[0], bH1[1]);
                    mma16816(sc[npp * 4 + 3], aS, bH1[2], bH1[3]);
                }
            }
            float mx0 = -1e30f, mx1 = -1e30f;
            #pragma unroll
            for (int nt = 0; nt < 16; nt++) {
                mx0 = fmaxf(mx0, fmaxf(sc[nt][0], sc[nt][1]));
                mx1 = fmaxf(mx1, fmaxf(sc[nt][2], sc[nt][3]));
            }
            mx0 = fmaxf(mx0, __shfl_xor_sync(0xffffffffu, mx0, 1));
            mx0 = fmaxf(mx0, __shfl_xor_sync(0xffffffffu, mx0, 2));
            mx1 = fmaxf(mx1, __shfl_xor_sync(0xffffffffu, mx1, 1));
            mx1 = fmaxf(mx1, __shfl_xor_sync(0xffffffffu, mx1, 2));
            float Z0 = 0.f, Z1 = 0.f;
            #pragma unroll
            for (int nt = 0; nt < 16; nt++) {
                sc[nt][0] = __expf(sc[nt][0] - mx0); Z0 += sc[nt][0];
                sc[nt][1] = __expf(sc[nt][1] - mx0); Z0 += sc[nt][1];
                sc[nt][2] = __expf(sc[nt][2] - mx1); Z1 += sc[nt][2];
                sc[nt][3] = __expf(sc[nt][3] - mx1); Z1 += sc[nt][3];
            }
            Z0 += __shfl_xor_sync(0xffffffffu, Z0, 1);
            Z0 += __shfl_xor_sync(0xffffffffu, Z0, 2);
            Z1 += __shfl_xor_sync(0xffffffffu, Z1, 1);
            Z1 += __shfl_xor_sync(0xffffffffu, Z1, 2);
            const float c0 = wos[s0 + gq]     / Z0;
            const float c1 = wos[s0 + 8 + gq] / Z1;
            #pragma unroll
            for (int nt = 0; nt < 16; nt++) {
                wacc[nt][0] += sc[nt][0] * c0 + sc[nt][2] * c1;
                wacc[nt][1] += sc[nt][1] * c0 + sc[nt][3] * c1;
            }
        }
        #pragma unroll
        for (int d = 4; d < 32; d <<= 1)
            #pragma unroll
            for (int nt = 0; nt < 16; nt++) {
                wacc[nt][0] += __shfl_xor_sync(0xffffffffu, wacc[nt][0], d);
                wacc[nt][1] += __shfl_xor_sync(0xffffffffu, wacc[nt][1], d);
            }
        if (lid < 4) {
            #pragma unroll
            for (int nt = 0; nt < 16; nt++) {
                atomicAdd(&wsm[head * 128 + nt * 8 + 2 * lid],     wacc[nt][0]);
                atomicAdd(&wsm[head * 128 + nt * 8 + 2 * lid + 1], wacc[nt][1]);
            }
        }
    }
    __syncthreads();

    // ================= Phase 3: out[b, g*128+f] = sum_t w[head][t]*x_h[b,f,t] + bo
    if (tid < 128) {
        const float* wv2 = wsm + (tid >> 6) * 128;
        const uint4* x8 = (const uint4*)(xbh + (size_t)(g * 128 + tid) * SEQ);
        float acc = 0.f;
        #pragma unroll 4
        for (int t8 = 0; t8 < 16; t8++) {
            uint4 v = x8[t8];
            const __half2* h = (const __half2*)&v;
            #pragma unroll
            for (int j = 0; j < 4; j++) {
                float2 f = __half22float2(h[j]);
                acc += f.x * wv2[t8 * 8 + j * 2] + f.y * wv2[t8 * 8 + j * 2 + 1];
            }
        }
        out[(size_t)b * FIN + g * 128 + tid] = acc + bo[0];
    }
}

extern "C" void kernel_launch(void* const* d_in, const int* in_sizes, int n_in,
                              void* d_out, int out_size)
{
    (void)in_sizes; (void)n_in; (void)out_size;
    const float* x  = (const float*)d_in[0];
    const float* Wq = (const float*)d_in[1];
    const float* bq = (const float*)d_in[2];
    const float* Wk = (const float*)d_in[3];
    const float* bk = (const float*)d_in[4];
    const float* Wo = (const float*)d_in[5];
    const float* bo = (const float*)d_in[6];
    float* out = (float*)d_out;

    prep_w_kernel<<<1024, 256>>>(Wq, Wk);
    prep_x_kernel<<<32768, 256>>>(x);

    cudaFuncSetAttribute(Attention_75402445849133_kernel,
                         cudaFuncAttributeMaxDynamicSharedMemorySize, SMEM_TOTAL);
    dim3 grid(8, 256, 1);
    Attention_75402445849133_kernel<<<grid, 256, SMEM_TOTAL>>>(bq, bk, Wo, bo, out);
}

// round 14
// speedup vs baseline: 1.9407x; 1.0226x over previous
#include <cuda_runtime.h>
#include <cuda_fp16.h>
#include <cstdint>

// ============ sm_103-safe primitives ============
__device__ __forceinline__ uint32_t smem_u32(const void* p) {
    uint32_t a;
    asm("{ .reg .u64 t; cvta.to.shared.u64 t, %1; cvt.u32.u64 %0, t; }" : "=r"(a) : "l"(p));
    return a;
}
__device__ __forceinline__ void ldsm4(uint32_t r[4], uint32_t addr) {
    asm volatile("ldmatrix.sync.aligned.m8n8.x4.shared.b16 {%0,%1,%2,%3}, [%4];"
                 : "=r"(r[0]), "=r"(r[1]), "=r"(r[2]), "=r"(r[3]) : "r"(addr));
}
__device__ __forceinline__ void ldsm4t(uint32_t r[4], uint32_t addr) {
    asm volatile("ldmatrix.sync.aligned.m8n8.x4.trans.shared.b16 {%0,%1,%2,%3}, [%4];"
                 : "=r"(r[0]), "=r"(r[1]), "=r"(r[2]), "=r"(r[3]) : "r"(addr));
}
__device__ __forceinline__ void mma16816(float c[4], const uint32_t a[4],
                                         uint32_t b0, uint32_t b1) {
    asm volatile(
        "mma.sync.aligned.m16n8k16.row.col.f32.f16.f16.f32 "
        "{%0,%1,%2,%3},{%4,%5,%6,%7},{%8,%9},{%0,%1,%2,%3};"
        : "+f"(c[0]), "+f"(c[1]), "+f"(c[2]), "+f"(c[3])
        : "r"(a[0]), "r"(a[1]), "r"(a[2]), "r"(a[3]), "r"(b0), "r"(b1));
}
__device__ __forceinline__ uint32_t pack2h(__half lo, __half hi) {
    return ((uint32_t)__half_as_ushort(hi) << 16) | (uint32_t)__half_as_ushort(lo);
}
__device__ __forceinline__ uint2 cvt4h(float4 v) {
    return make_uint2(pack2h(__float2half_rn(v.x), __float2half_rn(v.y)),
                      pack2h(__float2half_rn(v.z), __float2half_rn(v.w)));
}
__device__ __forceinline__ void cpa16(uint32_t dst, const void* src) {
    asm volatile("cp.async.cg.shared.global [%0], [%1], 16;" :: "r"(dst), "l"(src) : "memory");
}
#define CP_COMMIT() asm volatile("cp.async.commit_group;" ::: "memory")
#define CP_WAIT0()  asm volatile("cp.async.wait_group 0;" ::: "memory")
#define SWZ128(o) ((o) ^ (((o) >> 3) & 0x70))
#define SWZ256(o) ((o) ^ (((o) >> 4) & 0x70))

// ============ problem constants ============
#define FIN  1024
#define SEQ  128
#define CH   128           // K per chunk
#define NC   8             // chunks

// ============ pre-converted global staging (single fp16) ============
__device__ __align__(16) __half g_Wq[1024 * 1024];
__device__ __align__(16) __half g_Wk[1024 * 1024];
__device__ __align__(16) __half g_x[256 * 1024 * 128];

__global__ void __launch_bounds__(256) prep_w_kernel(const float* __restrict__ Wq,
                                                     const float* __restrict__ Wk) {
    int i = blockIdx.x * 256 + threadIdx.x;
    ((uint2*)g_Wq)[i] = cvt4h(((const float4*)Wq)[i]);
    ((uint2*)g_Wk)[i] = cvt4h(((const float4*)Wk)[i]);
}
__global__ void __launch_bounds__(256) prep_x_kernel(const float* __restrict__ x) {
    size_t i = (size_t)blockIdx.x * 256 + threadIdx.x;
    ((uint2*)g_x)[i] = cvt4h(((const float4*)x)[i]);
}

// ============ SMEM layout (bytes) ============
// 2-stage chunk buffers: [W 256x128 fp16 64K | x 128x128 fp16 32K] x 2 = 192K
#define BUF_SZ  98304
#define BW_S    0
#define BX_S    65536
#define KT_S    0              // overlays dead buffer-0 region after mainloop
#define QT_S    196608         // 2 heads x [128 s][64 d] fp16 (16K/head)
#define W_SM    229376
#define BQ_SM   230400
#define BK_SM   230912
#define WO_SM   231424
#define SMEM_TOTAL 231936

__global__ void __launch_bounds__(256, 1)
Attention_75402445849133_kernel(const float* __restrict__ bq, const float* __restrict__ bk,
                                const float* __restrict__ Wo, const float* __restrict__ bo,
                                float* __restrict__ out)
{
    extern __shared__ char smem[];
    const uint32_t sbase = smem_u32(smem);
    const int tid = threadIdx.x;
    const int w   = tid >> 5;
    const int lid = tid & 31;
    const int gq  = lid >> 2;
    const int tq  = lid & 3;
    const int g   = blockIdx.x;
    const int b   = blockIdx.y;

    float* wsm = (float*)(smem + W_SM);
    float* bqs = (float*)(smem + BQ_SM);
    float* bks = (float*)(smem + BK_SM);
    float* wos = (float*)(smem + WO_SM);
    if (tid < 128) {
        bqs[tid] = bq[g * 128 + tid];
        bks[tid] = bk[g * 128 + tid];
        wos[tid] = Wo[tid];
    }
    wsm[tid] = 0.0f;

    const __half* xbh = g_x + (size_t)b * FIN * SEQ;
    const __half* Wqb = g_Wq + (size_t)g * 128 * FIN;
    const __half* Wkb = g_Wk + (size_t)g * 128 * FIN;

    const int m0 = (w & 3) * 64;
    const int n0 = (w >> 2) * 64;

    float creg[4][8][4];
    #pragma unroll
    for (int a = 0; a < 4; a++)
        #pragma unroll
        for (int n = 0; n < 8; n++)
            #pragma unroll
            for (int j = 0; j < 4; j++) creg[a][n][j] = 0.f;

    // ---- chunk issue helper (inline addressing; W: 16 granules/thr, x: 8) ----
    // W chunk: 256 rows x 128 fp16 = 256B rows; x chunk: 128 rows x 128 fp16.
    // prologue: issue chunk 0 into buffer 0
    {
        #pragma unroll
        for (int j = 0; j < 16; j++) {
            int wi = j * 256 + tid;
            int row = wi >> 4, cg = wi & 15;
            uint32_t off = SWZ256((uint32_t)(row * 256 + cg * 16));
            const __half* src = (row < 128 ? Wqb : Wkb) + (size_t)(row & 127) * FIN + cg * 8;
            cpa16(sbase + BW_S + off, src);
        }
        #pragma unroll
        for (int j = 0; j < 8; j++) {
            int xi = j * 256 + tid;
            int xr = xi >> 4, xg = xi & 15;
            uint32_t off = SWZ256((uint32_t)(xr * 256 + xg * 16));
            cpa16(sbase + BX_S + off, xbh + (size_t)xr * SEQ + xg * 8);
        }
        CP_COMMIT();
    }

    // ================= fused Q+K projection mainloop (1 fp16 term) =============
    #pragma unroll 1
    for (int kc = 0; kc < NC; kc++) {
        CP_WAIT0();
        __syncthreads();   // chunk kc visible; all reads of buf (kc+1)&1 (chunk kc-1) done

        if (kc + 1 < NC) {
            const uint32_t nb = sbase + ((kc + 1) & 1) * BUF_SZ;
            const int kn = (kc + 1) * CH;
            #pragma unroll
            for (int j = 0; j < 16; j++) {
                int wi = j * 256 + tid;
                int row = wi >> 4, cg = wi & 15;
                uint32_t off = SWZ256((uint32_t)(row * 256 + cg * 16));
                const __half* src = (row < 128 ? Wqb : Wkb) + (size_t)(row & 127) * FIN + kn + cg * 8;
                cpa16(nb + BW_S + off, src);
            }
            #pragma unroll
            for (int j = 0; j < 8; j++) {
                int xi = j * 256 + tid;
                int xr = xi >> 4, xg = xi & 15;
                uint32_t off = SWZ256((uint32_t)(xr * 256 + xg * 16));
                cpa16(nb + BX_S + off, xbh + (size_t)(kn + xr) * SEQ + xg * 8);
            }
            CP_COMMIT();
        }

        const uint32_t bufb = sbase + (kc & 1) * BUF_SZ;
        #pragma unroll
        for (int ks = 0; ks < 8; ks++) {
            const int k0 = ks * 16;
            uint32_t aS[4][4];
            #pragma unroll
            for (int mt = 0; mt < 4; mt++) {
                int row = m0 + mt * 16 + (lid & 15);
                int col = k0 + ((lid >> 4) << 3);
                uint32_t off = SWZ256((uint32_t)(row * 256 + col * 2));
                ldsm4(aS[mt], bufb + BW_S + off);
            }
            const int tL  = lid >> 3;
            const int krw = k0 + ((tL & 1) << 3) + (lid & 7);
            uint32_t bCur[4], bNxt[4];
            {
                int nc = n0 + ((tL >> 1) << 3);
                ldsm4t(bCur, bufb + BX_S + SWZ256((uint32_t)(krw * 256 + nc * 2)));
            }
            #pragma unroll
            for (int np = 0; np < 4; np++) {
                if (np < 3) {
                    int nc = n0 + (np + 1) * 16 + ((tL >> 1) << 3);
                    ldsm4t(bNxt, bufb + BX_S + SWZ256((uint32_t)(krw * 256 + nc * 2)));
                }
                #pragma unroll
                for (int mt = 0; mt < 4; mt++) mma16816(creg[mt][np * 2],     aS[mt], bCur[0], bCur[1]);
                #pragma unroll
                for (int mt = 0; mt < 4; mt++) mma16816(creg[mt][np * 2 + 1], aS[mt], bCur[2], bCur[3]);
                #pragma unroll
                for (int j = 0; j < 4; j++) bCur[j] = bNxt[j];
            }
        }
    }

    // ---- writeback: stacked C -> qT / kT single fp16 (+bias; q scaled 1/8) ----
    // KT overlays buffer-0: all buffer-0 reads (chunk 6) retired before the kc=7
    // barrier; each warp writes only after finishing its own chunk-7 compute
    // (buffer 1). Phase-2 reads happen after the next __syncthreads.
    {
        #pragma unroll
        for (int mt = 0; mt < 4; mt++)
            #pragma unroll
            for (int rj = 0; rj < 2; rj++) {
                int m = m0 + mt * 16 + rj * 8 + gq;
                int isq = (m < 128);
                int mloc = m & 127;
                float bias = isq ? bqs[mloc] : bks[mloc];
                int head = mloc >> 6, d = mloc & 63;
                char* dh = smem + (isq ? QT_S : KT_S) + head * 16384;
                #pragma unroll
                for (int nt = 0; nt < 8; nt++)
                    #pragma unroll
                    for (int jj = 0; jj < 2; jj++) {
                        int n = n0 + nt * 8 + tq * 2 + jj;
                        float v = creg[mt][nt][rj * 2 + jj] + bias;
                        if (isq) v *= 0.125f;
                        uint32_t off = SWZ128((uint32_t)(n * 128 + d * 2));
                        *(__half*)(dh + off) = __float2half_rn(v);
                    }
            }
    }
    __syncthreads();

    // ================= Phase 2: scores (single fp16) + softmax + w reduction ====
    {
        const int head = w >> 2;
        const int sb0  = (w & 3) * 32;
        const uint32_t qh = sbase + QT_S + head * 16384;
        const uint32_t kh = sbase + KT_S + head * 16384;

        float wacc[16][2];
        #pragma unroll
        for (int nt = 0; nt < 16; nt++) { wacc[nt][0] = 0.f; wacc[nt][1] = 0.f; }

        #pragma unroll 1
        for (int chunk = 0; chunk < 2; chunk++) {
            const int s0 = sb0 + chunk * 16;
            float sc[16][4];
            #pragma unroll
            for (int nt = 0; nt < 16; nt++)
                #pragma unroll
                for (int j = 0; j < 4; j++) sc[nt][j] = 0.f;

            #pragma unroll
            for (int ks = 0; ks < 4; ks++) {
                const int k0 = ks * 16;
                uint32_t aS[4];
                {
                    int row = s0 + (lid & 15);
                    int col = k0 + ((lid >> 4) << 3);
                    uint32_t off = SWZ128((uint32_t)(row * 128 + col * 2));
                    ldsm4(aS, qh + off);
                }
                #pragma unroll
                for (int npp = 0; npp < 4; npp++) {
                    int tL = lid >> 3;
                    int ccol = k0 + ((tL & 1) << 3);
                    int r0 = (npp * 2) * 16 + ((tL >> 1) << 3) + (lid & 7);
                    int r1 = (npp * 2 + 1) * 16 + ((tL >> 1) << 3) + (lid & 7);
                    uint32_t bH0[4], bH1[4];
                    ldsm4(bH0, kh + SWZ128((uint32_t)(r0 * 128 + ccol * 2)));
                    ldsm4(bH1, kh + SWZ128((uint32_t)(r1 * 128 + ccol * 2)));
                    mma16816(sc[npp * 4 + 0], aS, bH0[0], bH0[1]);
                    mma16816(sc[npp * 4 + 1], aS, bH0[2], bH0[3]);
                    mma16816(sc[npp * 4 + 2], aS, bH1[0], bH1[1]);
                    mma16816(sc[npp * 4 + 3], aS, bH1[2], bH1[3]);
                }
            }
            float mx0 = -1e30f, mx1 = -1e30f;
            #pragma unroll
            for (int nt = 0; nt < 16; nt++) {
                mx0 = fmaxf(mx0, fmaxf(sc[nt][0], sc[nt][1]));
                mx1 = fmaxf(mx1, fmaxf(sc[nt][2], sc[nt][3]));
            }
            mx0 = fmaxf(mx0, __shfl_xor_sync(0xffffffffu, mx0, 1));
            mx0 = fmaxf(mx0, __shfl_xor_sync(0xffffffffu, mx0, 2));
            mx1 = fmaxf(mx1, __shfl_xor_sync(0xffffffffu, mx1, 1));
            mx1 = fmaxf(mx1, __shfl_xor_sync(0xffffffffu, mx1, 2));
            float Z0 = 0.f, Z1 = 0.f;
            #pragma unroll
            for (int nt = 0; nt < 16; nt++) {
                sc[nt][0] = __expf(sc[nt][0] - mx0); Z0 += sc[nt][0];
                sc[nt][1] = __expf(sc[nt][1] - mx0); Z0 += sc[nt][1];
                sc[nt][2] = __expf(sc[nt][2] - mx1); Z1 += sc[nt][2];
                sc[nt][3] = __expf(sc[nt][3] - mx1); Z1 += sc[nt][3];
            }
            Z0 += __shfl_xor_sync(0xffffffffu, Z0, 1);
            Z0 += __shfl_xor_sync(0xffffffffu, Z0, 2);
            Z1 += __shfl_xor_sync(0xffffffffu, Z1, 1);
            Z1 += __shfl_xor_sync(0xffffffffu, Z1, 2);
            const float c0 = wos[s0 + gq]     / Z0;
            const float c1 = wos[s0 + 8 + gq] / Z1;
            #pragma unroll
            for (int nt = 0; nt < 16; nt++) {
                wacc[nt][0] += sc[nt][0] * c0 + sc[nt][2] * c1;
                wacc[nt][1] += sc[nt][1] * c0 + sc[nt][3] * c1;
            }
        }
        #pragma unroll
        for (int d = 4; d < 32; d <<= 1)
            #pragma unroll
            for (int nt = 0; nt < 16; nt++) {
                wacc[nt][0] += __shfl_xor_sync(0xffffffffu, wacc[nt][0], d);
                wacc[nt][1] += __shfl_xor_sync(0xffffffffu, wacc[nt][1], d);
            }
        if (lid < 4) {
            #pragma unroll
            for (int nt = 0; nt < 16; nt++) {
                atomicAdd(&wsm[head * 128 + nt * 8 + 2 * lid],     wacc[nt][0]);
                atomicAdd(&wsm[head * 128 + nt * 8 + 2 * lid + 1], wacc[nt][1]);
            }
        }
    }
    __syncthreads();

    // ================= Phase 3: out[b, g*128+f] = sum_t w[head][t]*x_h[b,f,t] + bo
    if (tid < 128) {
        const float* wv2 = wsm + (tid >> 6) * 128;
        const uint4* x8 = (const uint4*)(xbh + (size_t)(g * 128 + tid) * SEQ);
        float acc = 0.f;
        #pragma unroll 4
        for (int t8 = 0; t8 < 16; t8++) {
            uint4 v = x8[t8];
            const __half2* h = (const __half2*)&v;
            #pragma unroll
            for (int j = 0; j < 4; j++) {
                float2 f = __half22float2(h[j]);
                acc += f.x * wv2[t8 * 8 + j * 2] + f.y * wv2[t8 * 8 + j * 2 + 1];
            }
        }
        out[(size_t)b * FIN + g * 128 + tid] = acc + bo[0];
    }
}

extern "C" void kernel_launch(void* const* d_in, const int* in_sizes, int n_in,
                              void* d_out, int out_size)
{
    (void)in_sizes; (void)n_in; (void)out_size;
    const float* x  = (const float*)d_in[0];
    const float* Wq = (const float*)d_in[1];
    const float* bq = (const float*)d_in[2];
    const float* Wk = (const float*)d_in[3];
    const float* bk = (const float*)d_in[4];
    const float* Wo = (const float*)d_in[5];
    const float* bo = (const float*)d_in[6];
    float* out = (float*)d_out;

    prep_w_kernel<<<1024, 256>>>(Wq, Wk);
    prep_x_kernel<<<32768, 256>>>(x);

    cudaFuncSetAttribute(Attention_75402445849133_kernel,
                         cudaFuncAttributeMaxDynamicSharedMemorySize, SMEM_TOTAL);
    dim3 grid(8, 256, 1);
    Attention_75402445849133_kernel<<<grid, 256, SMEM_TOTAL>>>(bq, bk, Wo, bo, out);
}

// round 15
// speedup vs baseline: 1.9475x; 1.0035x over previous
#include <cuda_runtime.h>
#include <cuda_fp16.h>
#include <cstdint>

// ============ sm_103-safe primitives ============
__device__ __forceinline__ uint32_t smem_u32(const void* p) {
    uint32_t a;
    asm("{ .reg .u64 t; cvta.to.shared.u64 t, %1; cvt.u32.u64 %0, t; }" : "=r"(a) : "l"(p));
    return a;
}
__device__ __forceinline__ void ldsm4(uint32_t r[4], uint32_t addr) {
    asm volatile("ldmatrix.sync.aligned.m8n8.x4.shared.b16 {%0,%1,%2,%3}, [%4];"
                 : "=r"(r[0]), "=r"(r[1]), "=r"(r[2]), "=r"(r[3]) : "r"(addr));
}
__device__ __forceinline__ void ldsm4t(uint32_t r[4], uint32_t addr) {
    asm volatile("ldmatrix.sync.aligned.m8n8.x4.trans.shared.b16 {%0,%1,%2,%3}, [%4];"
                 : "=r"(r[0]), "=r"(r[1]), "=r"(r[2]), "=r"(r[3]) : "r"(addr));
}
__device__ __forceinline__ void mma16816(float c[4], const uint32_t a[4],
                                         uint32_t b0, uint32_t b1) {
    asm volatile(
        "mma.sync.aligned.m16n8k16.row.col.f32.f16.f16.f32 "
        "{%0,%1,%2,%3},{%4,%5,%6,%7},{%8,%9},{%0,%1,%2,%3};"
        : "+f"(c[0]), "+f"(c[1]), "+f"(c[2]), "+f"(c[3])
        : "r"(a[0]), "r"(a[1]), "r"(a[2]), "r"(a[3]), "r"(b0), "r"(b1));
}
__device__ __forceinline__ uint32_t pack2h(__half lo, __half hi) {
    return ((uint32_t)__half_as_ushort(hi) << 16) | (uint32_t)__half_as_ushort(lo);
}
__device__ __forceinline__ uint2 cvt4h(float4 v) {
    return make_uint2(pack2h(__float2half_rn(v.x), __float2half_rn(v.y)),
                      pack2h(__float2half_rn(v.z), __float2half_rn(v.w)));
}
__device__ __forceinline__ void cpa16(uint32_t dst, const void* src) {
    asm volatile("cp.async.cg.shared.global [%0], [%1], 16;" :: "r"(dst), "l"(src) : "memory");
}
#define CP_COMMIT() asm volatile("cp.async.commit_group;" ::: "memory")
#define CP_WAIT0()  asm volatile("cp.async.wait_group 0;" ::: "memory")
#define SWZ128(o) ((o) ^ (((o) >> 3) & 0x70))
#define SWZ256(o) ((o) ^ (((o) >> 4) & 0x70))

// ============ problem constants ============
#define FIN  1024
#define SEQ  128
#define CH   128           // K per chunk
#define NC   8             // chunks

// ============ pre-converted global staging (single fp16) ============
__device__ __align__(16) __half g_Wq[1024 * 1024];
__device__ __align__(16) __half g_Wk[1024 * 1024];
__device__ __align__(16) __half g_x[256 * 1024 * 128];

__global__ void __launch_bounds__(256) prep_w_kernel(const float* __restrict__ Wq,
                                                     const float* __restrict__ Wk) {
    int base = blockIdx.x * 1024 + threadIdx.x;
    float4 v0 = ((const float4*)Wq)[base];
    float4 v1 = ((const float4*)Wq)[base + 256];
    float4 v2 = ((const float4*)Wq)[base + 512];
    float4 v3 = ((const float4*)Wq)[base + 768];
    float4 u0 = ((const float4*)Wk)[base];
    float4 u1 = ((const float4*)Wk)[base + 256];
    float4 u2 = ((const float4*)Wk)[base + 512];
    float4 u3 = ((const float4*)Wk)[base + 768];
    ((uint2*)g_Wq)[base]       = cvt4h(v0);
    ((uint2*)g_Wq)[base + 256] = cvt4h(v1);
    ((uint2*)g_Wq)[base + 512] = cvt4h(v2);
    ((uint2*)g_Wq)[base + 768] = cvt4h(v3);
    ((uint2*)g_Wk)[base]       = cvt4h(u0);
    ((uint2*)g_Wk)[base + 256] = cvt4h(u1);
    ((uint2*)g_Wk)[base + 512] = cvt4h(u2);
    ((uint2*)g_Wk)[base + 768] = cvt4h(u3);
}
__global__ void __launch_bounds__(256) prep_x_kernel(const float* __restrict__ x) {
    size_t base = (size_t)blockIdx.x * 1024 + threadIdx.x;
    float4 v0 = ((const float4*)x)[base];
    float4 v1 = ((const float4*)x)[base + 256];
    float4 v2 = ((const float4*)x)[base + 512];
    float4 v3 = ((const float4*)x)[base + 768];
    ((uint2*)g_x)[base]       = cvt4h(v0);
    ((uint2*)g_x)[base + 256] = cvt4h(v1);
    ((uint2*)g_x)[base + 512] = cvt4h(v2);
    ((uint2*)g_x)[base + 768] = cvt4h(v3);
}

// ============ SMEM layout (bytes) ============
// 2-stage chunk buffers: [W 256x128 fp16 64K | x 128x128 fp16 32K] x 2 = 192K
#define BUF_SZ  98304
#define BW_S    0
#define BX_S    65536
#define KT_S    0              // overlays dead buffer-0 region after mainloop
#define QT_S    196608         // 2 heads x [128 s][64 d] fp16 (16K/head)
#define W_SM    229376
#define BQ_SM   230400
#define BK_SM   230912
#define WO_SM   231424
#define SMEM_TOTAL 231936

__global__ void __launch_bounds__(256, 1)
Attention_75402445849133_kernel(const float* __restrict__ bq, const float* __restrict__ bk,
                                const float* __restrict__ Wo, const float* __restrict__ bo,
                                float* __restrict__ out)
{
    extern __shared__ char smem[];
    const uint32_t sbase = smem_u32(smem);
    const int tid = threadIdx.x;
    const int w   = tid >> 5;
    const int lid = tid & 31;
    const int gq  = lid >> 2;
    const int tq  = lid & 3;
    const int g   = blockIdx.x;
    const int b   = blockIdx.y;

    float* wsm = (float*)(smem + W_SM);
    float* bqs = (float*)(smem + BQ_SM);
    float* bks = (float*)(smem + BK_SM);
    float* wos = (float*)(smem + WO_SM);
    if (tid < 128) {
        bqs[tid] = bq[g * 128 + tid];
        bks[tid] = bk[g * 128 + tid];
        wos[tid] = Wo[tid];
    }
    wsm[tid] = 0.0f;

    const __half* xbh = g_x + (size_t)b * FIN * SEQ;
    const __half* Wqb = g_Wq + (size_t)g * 128 * FIN;
    const __half* Wkb = g_Wk + (size_t)g * 128 * FIN;

    const int m0 = (w & 3) * 64;
    const int n0 = (w >> 2) * 64;
    const int tL = lid >> 3;

    float creg[4][8][4];
    #pragma unroll
    for (int a = 0; a < 4; a++)
        #pragma unroll
        for (int n = 0; n < 8; n++)
            #pragma unroll
            for (int j = 0; j < 4; j++) creg[a][n][j] = 0.f;

    // prologue: issue chunk 0 into buffer 0
    {
        #pragma unroll
        for (int j = 0; j < 16; j++) {
            int wi = j * 256 + tid;
            int row = wi >> 4, cg = wi & 15;
            uint32_t off = SWZ256((uint32_t)(row * 256 + cg * 16));
            const __half* src = (row < 128 ? Wqb : Wkb) + (size_t)(row & 127) * FIN + cg * 8;
            cpa16(sbase + BW_S + off, src);
        }
        #pragma unroll
        for (int j = 0; j < 8; j++) {
            int xi = j * 256 + tid;
            int xr = xi >> 4, xg = xi & 15;
            uint32_t off = SWZ256((uint32_t)(xr * 256 + xg * 16));
            cpa16(sbase + BX_S + off, xbh + (size_t)xr * SEQ + xg * 8);
        }
        CP_COMMIT();
    }

    // ================= fused Q+K projection mainloop (fully pipelined) =========
    #pragma unroll 1
    for (int kc = 0; kc < NC; kc++) {
        CP_WAIT0();
        __syncthreads();

        if (kc + 1 < NC) {
            const uint32_t nb = sbase + ((kc + 1) & 1) * BUF_SZ;
            const int kn = (kc + 1) * CH;
            #pragma unroll
            for (int j = 0; j < 16; j++) {
                int wi = j * 256 + tid;
                int row = wi >> 4, cg = wi & 15;
                uint32_t off = SWZ256((uint32_t)(row * 256 + cg * 16));
                const __half* src = (row < 128 ? Wqb : Wkb) + (size_t)(row & 127) * FIN + kn + cg * 8;
                cpa16(nb + BW_S + off, src);
            }
            #pragma unroll
            for (int j = 0; j < 8; j++) {
                int xi = j * 256 + tid;
                int xr = xi >> 4, xg = xi & 15;
                uint32_t off = SWZ256((uint32_t)(xr * 256 + xg * 16));
                cpa16(nb + BX_S + off, xbh + (size_t)(kn + xr) * SEQ + xg * 8);
            }
            CP_COMMIT();
        }

        const uint32_t bufb = sbase + (kc & 1) * BUF_SZ;
        // A double-buffer + B one-step-ahead pipeline over 32 flattened steps
        uint32_t aA[2][4][4];
        #pragma unroll
        for (int mt = 0; mt < 4; mt++) {
            int row = m0 + mt * 16 + (lid & 15);
            int col = ((lid >> 4) << 3);
            ldsm4(aA[0][mt], bufb + BW_S + SWZ256((uint32_t)(row * 256 + col * 2)));
        }
        uint32_t bCur[4], bNxt[4];
        {
            int krw = ((tL & 1) << 3) + (lid & 7);
            int nc  = n0 + ((tL >> 1) << 3);
            ldsm4t(bCur, bufb + BX_S + SWZ256((uint32_t)(krw * 256 + nc * 2)));
        }
        #pragma unroll
        for (int step = 0; step < 32; step++) {
            const int ks = step >> 2, np = step & 3;
            const int cur = ks & 1;
            if (step < 31) {
                int ks2 = (step + 1) >> 2, np2 = (step + 1) & 3;
                int krw2 = ks2 * 16 + ((tL & 1) << 3) + (lid & 7);
                int nc2  = n0 + np2 * 16 + ((tL >> 1) << 3);
                ldsm4t(bNxt, bufb + BX_S + SWZ256((uint32_t)(krw2 * 256 + nc2 * 2)));
            }
            if (np == 0 && ks < 7) {
                #pragma unroll
                for (int mt = 0; mt < 4; mt++) {
                    int row = m0 + mt * 16 + (lid & 15);
                    int col = (ks + 1) * 16 + ((lid >> 4) << 3);
                    ldsm4(aA[cur ^ 1][mt], bufb + BW_S + SWZ256((uint32_t)(row * 256 + col * 2)));
                }
            }
            #pragma unroll
            for (int mt = 0; mt < 4; mt++) mma16816(creg[mt][np * 2],     aA[cur][mt], bCur[0], bCur[1]);
            #pragma unroll
            for (int mt = 0; mt < 4; mt++) mma16816(creg[mt][np * 2 + 1], aA[cur][mt], bCur[2], bCur[3]);
            #pragma unroll
            for (int j = 0; j < 4; j++) bCur[j] = bNxt[j];
        }
    }

    // ---- writeback: stacked C -> qT / kT single fp16 (+bias; q scaled 1/8) ----
    {
        #pragma unroll
        for (int mt = 0; mt < 4; mt++)
            #pragma unroll
            for (int rj = 0; rj < 2; rj++) {
                int m = m0 + mt * 16 + rj * 8 + gq;
                int isq = (m < 128);
                int mloc = m & 127;
                float bias = isq ? bqs[mloc] : bks[mloc];
                int head = mloc >> 6, d = mloc & 63;
                char* dh = smem + (isq ? QT_S : KT_S) + head * 16384;
                #pragma unroll
                for (int nt = 0; nt < 8; nt++)
                    #pragma unroll
                    for (int jj = 0; jj < 2; jj++) {
                        int n = n0 + nt * 8 + tq * 2 + jj;
                        float v = creg[mt][nt][rj * 2 + jj] + bias;
                        if (isq) v *= 0.125f;
                        uint32_t off = SWZ128((uint32_t)(n * 128 + d * 2));
                        *(__half*)(dh + off) = __float2half_rn(v);
                    }
            }
    }
    __syncthreads();

    // ================= Phase 2: scores (single fp16) + softmax + w reduction ====
    {
        const int head = w >> 2;
        const int sb0  = (w & 3) * 32;
        const uint32_t qh = sbase + QT_S + head * 16384;
        const uint32_t kh = sbase + KT_S + head * 16384;

        float wacc[16][2];
        #pragma unroll
        for (int nt = 0; nt < 16; nt++) { wacc[nt][0] = 0.f; wacc[nt][1] = 0.f; }

        #pragma unroll 1
        for (int chunk = 0; chunk < 2; chunk++) {
            const int s0 = sb0 + chunk * 16;
            float sc[16][4];
            #pragma unroll
            for (int nt = 0; nt < 16; nt++)
                #pragma unroll
                for (int j = 0; j < 4; j++) sc[nt][j] = 0.f;

            #pragma unroll
            for (int ks = 0; ks < 4; ks++) {
                const int k0 = ks * 16;
                uint32_t aS[4];
                {
                    int row = s0 + (lid & 15);
                    int col = k0 + ((lid >> 4) << 3);
                    uint32_t off = SWZ128((uint32_t)(row * 128 + col * 2));
                    ldsm4(aS, qh + off);
                }
                #pragma unroll
                for (int npp = 0; npp < 4; npp++) {
                    int ccol = k0 + ((tL & 1) << 3);
                    int r0 = (npp * 2) * 16 + ((tL >> 1) << 3) + (lid & 7);
                    int r1 = (npp * 2 + 1) * 16 + ((tL >> 1) << 3) + (lid & 7);
                    uint32_t bH0[4], bH1[4];
                    ldsm4(bH0, kh + SWZ128((uint32_t)(r0 * 128 + ccol * 2)));
                    ldsm4(bH1, kh + SWZ128((uint32_t)(r1 * 128 + ccol * 2)));
                    mma16816(sc[npp * 4 + 0], aS, bH0[0], bH0[1]);
                    mma16816(sc[npp * 4 + 1], aS, bH0[2], bH0[3]);
                    mma16816(sc[npp * 4 + 2], aS, bH1[0], bH1[1]);
                    mma16816(sc[npp * 4 + 3], aS, bH1[2], bH1[3]);
                }
            }
            float mx0 = -1e30f, mx1 = -1e30f;
            #pragma unroll
            for (int nt = 0; nt < 16; nt++) {
                mx0 = fmaxf(mx0, fmaxf(sc[nt][0], sc[nt][1]));
                mx1 = fmaxf(mx1, fmaxf(sc[nt][2], sc[nt][3]));
            }
            mx0 = fmaxf(mx0, __shfl_xor_sync(0xffffffffu, mx0, 1));
            mx0 = fmaxf(mx0, __shfl_xor_sync(0xffffffffu, mx0, 2));
            mx1 = fmaxf(mx1, __shfl_xor_sync(0xffffffffu, mx1, 1));
            mx1 = fmaxf(mx1, __shfl_xor_sync(0xffffffffu, mx1, 2));
            float Z0 = 0.f, Z1 = 0.f;
            #pragma unroll
            for (int nt = 0; nt < 16; nt++) {
                sc[nt][0] = __expf(sc[nt][0] - mx0); Z0 += sc[nt][0];
                sc[nt][1] = __expf(sc[nt][1] - mx0); Z0 += sc[nt][1];
                sc[nt][2] = __expf(sc[nt][2] - mx1); Z1 += sc[nt][2];
                sc[nt][3] = __expf(sc[nt][3] - mx1); Z1 += sc[nt][3];
            }
            Z0 += __shfl_xor_sync(0xffffffffu, Z0, 1);
            Z0 += __shfl_xor_sync(0xffffffffu, Z0, 2);
            Z1 += __shfl_xor_sync(0xffffffffu, Z1, 1);
            Z1 += __shfl_xor_sync(0xffffffffu, Z1, 2);
            const float c0 = wos[s0 + gq]     / Z0;
            const float c1 = wos[s0 + 8 + gq] / Z1;
            #pragma unroll
            for (int nt = 0; nt < 16; nt++) {
                wacc[nt][0] += sc[nt][0] * c0 + sc[nt][2] * c1;
                wacc[nt][1] += sc[nt][1] * c0 + sc[nt][3] * c1;
            }
        }
        #pragma unroll
        for (int d = 4; d < 32; d <<= 1)
            #pragma unroll
            for (int nt = 0; nt < 16; nt++) {
                wacc[nt][0] += __shfl_xor_sync(0xffffffffu, wacc[nt][0], d);
                wacc[nt][1] += __shfl_xor_sync(0xffffffffu, wacc[nt][1], d);
            }
        if (lid < 4) {
            #pragma unroll
            for (int nt = 0; nt < 16; nt++) {
                atomicAdd(&wsm[head * 128 + nt * 8 + 2 * lid],     wacc[nt][0]);
                atomicAdd(&wsm[head * 128 + nt * 8 + 2 * lid + 1], wacc[nt][1]);
            }
        }
    }
    __syncthreads();

    // ================= Phase 3: out[b, g*128+f] = sum_t w[head][t]*x_h[b,f,t] + bo
    if (tid < 128) {
        const float* wv2 = wsm + (tid >> 6) * 128;
        const uint4* x8 = (const uint4*)(xbh + (size_t)(g * 128 + tid) * SEQ);
        float acc = 0.f;
        #pragma unroll 4
        for (int t8 = 0; t8 < 16; t8++) {
            uint4 v = x8[t8];
            const __half2* h = (const __half2*)&v;
            #pragma unroll
            for (int j = 0; j < 4; j++) {
                float2 f = __half22float2(h[j]);
                acc += f.x * wv2[t8 * 8 + j * 2] + f.y * wv2[t8 * 8 + j * 2 + 1];
            }
        }
        out[(size_t)b * FIN + g * 128 + tid] = acc + bo[0];
    }
}

extern "C" void kernel_launch(void* const* d_in, const int* in_sizes, int n_in,
                              void* d_out, int out_size)
{
    (void)in_sizes; (void)n_in; (void)out_size;
    const float* x  = (const float*)d_in[0];
    const float* Wq = (const float*)d_in[1];
    const float* bq = (const float*)d_in[2];
    const float* Wk = (const float*)d_in[3];
    const float* bk = (const float*)d_in[4];
    const float* Wo = (const float*)d_in[5];
    const float* bo = (const float*)d_in[6];
    float* out = (float*)d_out;

    prep_w_kernel<<<256, 256>>>(Wq, Wk);
    prep_x_kernel<<<8192, 256>>>(x);

    cudaFuncSetAttribute(Attention_75402445849133_kernel,
                         cudaFuncAttributeMaxDynamicSharedMemorySize, SMEM_TOTAL);
    dim3 grid(8, 256, 1);
    Attention_75402445849133_kernel<<<grid, 256, SMEM_TOTAL>>>(bq, bk, Wo, bo, out);
}